// round 2
// baseline (speedup 1.0000x reference)
#include <cuda_runtime.h>

#define NM 64
#define MAXN 262144

typedef unsigned long long ull;

// ---------------- f32x2 packed helpers (sm_100+) ---------------------------
__device__ __forceinline__ ull f2pack(float lo, float hi) {
    ull d; asm("mov.b64 %0, {%1, %2};" : "=l"(d) : "f"(lo), "f"(hi)); return d;
}
__device__ __forceinline__ void f2unpack(ull v, float& lo, float& hi) {
    asm("mov.b64 {%0, %1}, %2;" : "=f"(lo), "=f"(hi) : "l"(v));
}
__device__ __forceinline__ ull fma2(ull a, ull b, ull c) {
    ull d; asm("fma.rn.f32x2 %0, %1, %2, %3;" : "=l"(d) : "l"(a), "l"(b), "l"(c)); return d;
}
__device__ __forceinline__ ull add2(ull a, ull b) {
    ull d; asm("add.rn.f32x2 %0, %1, %2;" : "=l"(d) : "l"(a), "l"(b)); return d;
}
__device__ __forceinline__ ull mul2(ull a, ull b) {
    ull d; asm("mul.rn.f32x2 %0, %1, %2;" : "=l"(d) : "l"(a), "l"(b)); return d;
}
#define NEG1X2 0xBF800000BF800000ULL  // {-1.0f, -1.0f}

// ---------------- scratch (device globals; no runtime allocation) ----------
__device__ int g_counts[NM];
__device__ int g_offsets[NM];
__device__ int g_cursor[NM];
__device__ int g_perm[MAXN];

// ---------------- prep kernels --------------------------------------------
__global__ void zero_kernel() {
    if (threadIdx.x < NM) g_counts[threadIdx.x] = 0;
}

__global__ void hist_kernel(const int* __restrict__ idx, int N) {
    __shared__ int lc[NM];
    if (threadIdx.x < NM) lc[threadIdx.x] = 0;
    __syncthreads();
    for (int i = blockIdx.x * blockDim.x + threadIdx.x; i < N; i += gridDim.x * blockDim.x)
        atomicAdd(&lc[idx[i]], 1);
    __syncthreads();
    if (threadIdx.x < NM) atomicAdd(&g_counts[threadIdx.x], lc[threadIdx.x]);
}

__global__ void scan_kernel() {
    __shared__ int s[NM];
    int t = threadIdx.x;
    s[t] = g_counts[t];
    __syncthreads();
    if (t == 0) {
        int acc = 0;
        for (int i = 0; i < NM; i++) { int c = s[i]; s[i] = acc; acc += c; }
    }
    __syncthreads();
    g_offsets[t] = s[t];
    g_cursor[t]  = s[t];
}

__global__ void scatter_kernel(const int* __restrict__ idx, int N) {
    __shared__ int lc[NM];
    __shared__ int lbase[NM];
    int t = threadIdx.x;
    int per = (N + gridDim.x - 1) / gridDim.x;
    int lo = blockIdx.x * per;
    int hi = min(lo + per, N);
    if (t < NM) lc[t] = 0;
    __syncthreads();
    for (int i = lo + t; i < hi; i += blockDim.x)
        atomicAdd(&lc[idx[i]], 1);
    __syncthreads();
    if (t < NM) { lbase[t] = atomicAdd(&g_cursor[t], lc[t]); lc[t] = 0; }
    __syncthreads();
    for (int i = lo + t; i < hi; i += blockDim.x) {
        int m = idx[i];
        int r = atomicAdd(&lc[m], 1);
        g_perm[lbase[m] + r] = i;
    }
}

// ---------------- main compute kernel -------------------------------------
// SMEM layout (floats):
//   [0, 12288)      W1, W2, W3 (3 x 64x64)
//   [12288, 12672)  W0 (64x6)
//   [12672, 12864)  W4 (3x64)
//   [12864, 13056)  B0|G0|H0 (64 each)
//   [13056, 13632)  layers 1..3: B|G|H (192 floats each layer)
//   [13632, 13636)  B4 (3 + pad)
#define SMEM_FLOATS 13636

// Packed LayerNorm + ReLU over 32 f32x2 pairs. g2/h2 point to packed G/H in smem.
__device__ __forceinline__ void ln_relu2(ull* __restrict__ hp, const ull* __restrict__ np,
                                         const ull* __restrict__ g2, const ull* __restrict__ h2) {
    ull s0 = np[0], s1 = np[1], s2 = np[2], s3 = np[3];
#pragma unroll
    for (int i = 4; i < 32; i += 4) {
        s0 = add2(s0, np[i]);     s1 = add2(s1, np[i + 1]);
        s2 = add2(s2, np[i + 2]); s3 = add2(s3, np[i + 3]);
    }
    s0 = add2(add2(s0, s1), add2(s2, s3));
    float a, b; f2unpack(s0, a, b);
    float mu = (a + b) * 0.015625f;
    ull mu2 = f2pack(mu, mu);

    ull v0 = 0ULL, v1 = 0ULL, v2 = 0ULL, v3 = 0ULL;
#pragma unroll
    for (int i = 0; i < 32; i += 4) {
        ull d0 = fma2(mu2, NEG1X2, np[i]);     v0 = fma2(d0, d0, v0);
        ull d1 = fma2(mu2, NEG1X2, np[i + 1]); v1 = fma2(d1, d1, v1);
        ull d2 = fma2(mu2, NEG1X2, np[i + 2]); v2 = fma2(d2, d2, v2);
        ull d3 = fma2(mu2, NEG1X2, np[i + 3]); v3 = fma2(d3, d3, v3);
    }
    v0 = add2(add2(v0, v1), add2(v2, v3));
    f2unpack(v0, a, b);
    float rs = rsqrtf((a + b) * 0.015625f + 1e-5f);
    ull rs2 = f2pack(rs, rs);

#pragma unroll
    for (int i = 0; i < 32; i++) {
        ull d = fma2(mu2, NEG1X2, np[i]);
        ull t = fma2(mul2(d, rs2), g2[i], h2[i]);
        float lo, hi; f2unpack(t, lo, hi);
        hp[i] = f2pack(fmaxf(lo, 0.0f), fmaxf(hi, 0.0f));
    }
}

__global__ void __launch_bounds__(256, 1) mlp_kernel(
    const float* __restrict__ x,
    const float* __restrict__ W0, const float* __restrict__ B0,
    const float* __restrict__ G0, const float* __restrict__ H0,
    const float* __restrict__ W1, const float* __restrict__ B1,
    const float* __restrict__ G1, const float* __restrict__ H1,
    const float* __restrict__ W2, const float* __restrict__ B2,
    const float* __restrict__ G2, const float* __restrict__ H2,
    const float* __restrict__ W3, const float* __restrict__ B3,
    const float* __restrict__ G3, const float* __restrict__ H3,
    const float* __restrict__ W4, const float* __restrict__ B4,
    float* __restrict__ out)
{
    extern __shared__ float sm[];
    const int tid = threadIdx.x;
    const int m = blockIdx.y;
    const int cnt = g_counts[m];
    if ((int)blockIdx.x * 256 >= cnt) return;
    const int base = g_offsets[m];

    float* sW    = sm;
    float* sW0   = sm + 12288;
    float* sW4   = sm + 12672;
    float* sBGH0 = sm + 12864;
    float* sBGH  = sm + 13056;
    float* sB4   = sm + 13632;

    // cooperative weight load (float4)
    {
        float4* d = (float4*)sW;
        const float4* s1 = (const float4*)(W1 + m * 4096);
        const float4* s2 = (const float4*)(W2 + m * 4096);
        const float4* s3 = (const float4*)(W3 + m * 4096);
        for (int i = tid; i < 1024; i += 256) { d[i] = s1[i]; d[1024 + i] = s2[i]; d[2048 + i] = s3[i]; }
        if (tid < 96) ((float4*)sW0)[tid] = ((const float4*)(W0 + m * 384))[tid];
        if (tid < 48) ((float4*)sW4)[tid] = ((const float4*)(W4 + m * 192))[tid];
        if (tid < 16) {
            ((float4*)(sBGH0      ))[tid] = ((const float4*)(B0 + m * 64))[tid];
            ((float4*)(sBGH0 +  64))[tid] = ((const float4*)(G0 + m * 64))[tid];
            ((float4*)(sBGH0 + 128))[tid] = ((const float4*)(H0 + m * 64))[tid];
            ((float4*)(sBGH       ))[tid] = ((const float4*)(B1 + m * 64))[tid];
            ((float4*)(sBGH  +  64))[tid] = ((const float4*)(G1 + m * 64))[tid];
            ((float4*)(sBGH  + 128))[tid] = ((const float4*)(H1 + m * 64))[tid];
            ((float4*)(sBGH  + 192))[tid] = ((const float4*)(B2 + m * 64))[tid];
            ((float4*)(sBGH  + 256))[tid] = ((const float4*)(G2 + m * 64))[tid];
            ((float4*)(sBGH  + 320))[tid] = ((const float4*)(H2 + m * 64))[tid];
            ((float4*)(sBGH  + 384))[tid] = ((const float4*)(B3 + m * 64))[tid];
            ((float4*)(sBGH  + 448))[tid] = ((const float4*)(G3 + m * 64))[tid];
            ((float4*)(sBGH  + 512))[tid] = ((const float4*)(H3 + m * 64))[tid];
        }
        if (tid < 3) sB4[tid] = B4[m * 3 + tid];
    }
    __syncthreads();

    for (int pos0 = blockIdx.x * 256; pos0 < cnt; pos0 += gridDim.x * 256) {
        const int pos = pos0 + tid;
        const bool active = pos < cnt;
        const int s = active ? g_perm[base + pos] : 0;

        float xin[6];
#pragma unroll
        for (int j = 0; j < 6; j++) xin[j] = active ? x[s * 6 + j] : 0.0f;

        ull hp[32], np[32];

        // layer 0: 6 -> 64 (scalar, then pack pairs)
#pragma unroll
        for (int o = 0; o < 64; o += 2) {
            float a0 = sBGH0[o], a1 = sBGH0[o + 1];
#pragma unroll
            for (int f = 0; f < 6; f++) {
                a0 = fmaf(sW0[o * 6 + f],       xin[f], a0);
                a1 = fmaf(sW0[(o + 1) * 6 + f], xin[f], a1);
            }
            np[o >> 1] = f2pack(a0, a1);
        }
        ln_relu2(hp, np, (const ull*)(sBGH0 + 64), (const ull*)(sBGH0 + 128));

        // layers 1..3: 64 -> 64, packed f32x2
#pragma unroll 1
        for (int l = 0; l < 3; l++) {
            const float* Wl = sW + l * 4096;
            const float* Bl = sBGH + l * 192;
#pragma unroll
            for (int o = 0; o < 64; o += 2) {
                const ulonglong2* w0 = (const ulonglong2*)(Wl + o * 64);
                const ulonglong2* w1 = (const ulonglong2*)(Wl + (o + 1) * 64);
                ull a0 = 0ULL, a1 = 0ULL, b0 = 0ULL, b1 = 0ULL;
#pragma unroll
                for (int f = 0; f < 16; f++) {
                    ulonglong2 wa = w0[f];
                    ulonglong2 wb = w1[f];
                    a0 = fma2(wa.x, hp[2 * f],     a0);
                    a1 = fma2(wa.y, hp[2 * f + 1], a1);
                    b0 = fma2(wb.x, hp[2 * f],     b0);
                    b1 = fma2(wb.y, hp[2 * f + 1], b1);
                }
                float xlo, xhi, ylo, yhi;
                f2unpack(add2(a0, a1), xlo, xhi);
                f2unpack(add2(b0, b1), ylo, yhi);
                np[o >> 1] = f2pack(xlo + xhi + Bl[o], ylo + yhi + Bl[o + 1]);
            }
            ln_relu2(hp, np, (const ull*)(Bl + 64), (const ull*)(Bl + 128));
        }

        // final layer: 64 -> 3, packed
        if (active) {
            float* op = out + s * 3;
#pragma unroll
            for (int o = 0; o < 3; o++) {
                const ull* w = (const ull*)(sW4 + o * 64);
                ull a0 = 0ULL, a1 = 0ULL;
#pragma unroll
                for (int f = 0; f < 32; f += 2) {
                    a0 = fma2(w[f],     hp[f],     a0);
                    a1 = fma2(w[f + 1], hp[f + 1], a1);
                }
                float lo, hi;
                f2unpack(add2(a0, a1), lo, hi);
                op[o] = lo + hi + sB4[o];
            }
        }
    }
}

// ---------------- launch ---------------------------------------------------
extern "C" void kernel_launch(void* const* d_in, const int* in_sizes, int n_in,
                              void* d_out, int out_size) {
    const float* x  = (const float*)d_in[0];
    const int* idx  = (const int*)d_in[1];
    const float* W0 = (const float*)d_in[2];
    const float* B0 = (const float*)d_in[3];
    const float* G0 = (const float*)d_in[4];
    const float* H0 = (const float*)d_in[5];
    const float* W1 = (const float*)d_in[6];
    const float* B1 = (const float*)d_in[7];
    const float* G1 = (const float*)d_in[8];
    const float* H1 = (const float*)d_in[9];
    const float* W2 = (const float*)d_in[10];
    const float* B2 = (const float*)d_in[11];
    const float* G2 = (const float*)d_in[12];
    const float* H2 = (const float*)d_in[13];
    const float* W3 = (const float*)d_in[14];
    const float* B3 = (const float*)d_in[15];
    const float* G3 = (const float*)d_in[16];
    const float* H3 = (const float*)d_in[17];
    const float* W4 = (const float*)d_in[18];
    const float* B4 = (const float*)d_in[19];
    float* out = (float*)d_out;

    int N = in_sizes[1];
    if (N > MAXN) N = MAXN;

    cudaFuncSetAttribute(mlp_kernel, cudaFuncAttributeMaxDynamicSharedMemorySize,
                         SMEM_FLOATS * (int)sizeof(float));

    zero_kernel<<<1, 64>>>();
    hist_kernel<<<256, 256>>>(idx, N);
    scan_kernel<<<1, 64>>>();
    scatter_kernel<<<256, 256>>>(idx, N);

    dim3 grid(17, 64);
    mlp_kernel<<<grid, 256, SMEM_FLOATS * (int)sizeof(float)>>>(
        x, W0, B0, G0, H0, W1, B1, G1, H1, W2, B2, G2, H2, W3, B3, G3, H3, W4, B4, out);
}

// round 4
// speedup vs baseline: 3.4682x; 3.4682x over previous
#include <cuda_runtime.h>
#include <cstdint>

#define NM 64
#define MAXN 262144

// ---------------- scratch ---------------------------------------------------
__device__ int g_counts[NM];
__device__ int g_offsets[NM];
__device__ int g_cursor[NM];
__device__ int g_perm[MAXN];

// ---------------- prep kernels ----------------------------------------------
__global__ void zero_kernel() {
    if (threadIdx.x < NM) g_counts[threadIdx.x] = 0;
}

__global__ void hist_kernel(const int* __restrict__ idx, int N) {
    __shared__ int lc[NM];
    if (threadIdx.x < NM) lc[threadIdx.x] = 0;
    __syncthreads();
    for (int i = blockIdx.x * blockDim.x + threadIdx.x; i < N; i += gridDim.x * blockDim.x)
        atomicAdd(&lc[idx[i]], 1);
    __syncthreads();
    if (threadIdx.x < NM) atomicAdd(&g_counts[threadIdx.x], lc[threadIdx.x]);
}

__global__ void scan_kernel() {
    __shared__ int s[NM];
    int t = threadIdx.x;
    s[t] = g_counts[t];
    __syncthreads();
    if (t == 0) {
        int acc = 0;
        for (int i = 0; i < NM; i++) { int c = s[i]; s[i] = acc; acc += c; }
    }
    __syncthreads();
    g_offsets[t] = s[t];
    g_cursor[t]  = s[t];
}

__global__ void scatter_kernel(const int* __restrict__ idx, int N) {
    __shared__ int lc[NM];
    __shared__ int lbase[NM];
    int t = threadIdx.x;
    int per = (N + gridDim.x - 1) / gridDim.x;
    int lo = blockIdx.x * per;
    int hi = min(lo + per, N);
    if (t < NM) lc[t] = 0;
    __syncthreads();
    for (int i = lo + t; i < hi; i += blockDim.x)
        atomicAdd(&lc[idx[i]], 1);
    __syncthreads();
    if (t < NM) { lbase[t] = atomicAdd(&g_cursor[t], lc[t]); lc[t] = 0; }
    __syncthreads();
    for (int i = lo + t; i < hi; i += blockDim.x) {
        int m = idx[i];
        int r = atomicAdd(&lc[m], 1);
        g_perm[lbase[m] + r] = i;
    }
}

// ---------------- mma helpers ------------------------------------------------
__device__ __forceinline__ uint32_t cvt_tf32(float f) {
    uint32_t u; asm("cvt.rna.tf32.f32 %0, %1;" : "=r"(u) : "f"(f)); return u;
}

__device__ __forceinline__ void mma_tf32(float* d, const uint32_t* a, uint32_t b0, uint32_t b1) {
    asm volatile(
        "mma.sync.aligned.m16n8k8.row.col.f32.tf32.tf32.f32 "
        "{%0,%1,%2,%3}, {%4,%5,%6,%7}, {%8,%9}, {%0,%1,%2,%3};"
        : "+f"(d[0]), "+f"(d[1]), "+f"(d[2]), "+f"(d[3])
        : "r"(a[0]), "r"(a[1]), "r"(a[2]), "r"(a[3]), "r"(b0), "r"(b1));
}

// ---------------- SMEM layout (floats) ---------------------------------------
#define OFF_STAGE 0        // 128 x 12 (tf32 bits of x, padded K=8, stride 12)
#define OFF_B0F   1536     // layer0 B frags: 8nn x 32 lanes x float2 = 512
#define OFF_BF    2048     // layers 1..3 B frags: 3 x 4096
#define OFF_GH0   14336    // G0|H0 (128)
#define OFF_BGH   14464    // layers 1..3: B|G|H (192 each) = 576
#define OFF_W4    15040    // 192
#define OFF_B4    15232    // 4
#define SMEM_FLOATS 15236

// LayerNorm + ReLU on one warp m-tile held as D fragments v[8][4].
// Thread lane = g*4+q holds rows {g, g+8}, cols {8nn+2q, 8nn+2q+1}.
__device__ __forceinline__ void ln16(float v[8][4], const float* pB,
                                     const float* pG, const float* pH, int q) {
    if (pB) {
#pragma unroll
        for (int nn = 0; nn < 8; nn++) {
            float2 bb = *(const float2*)(pB + nn * 8 + 2 * q);
            v[nn][0] += bb.x; v[nn][1] += bb.y;
            v[nn][2] += bb.x; v[nn][3] += bb.y;
        }
    }
    float s0 = 0.f, s1 = 0.f, q0 = 0.f, q1 = 0.f;
#pragma unroll
    for (int nn = 0; nn < 8; nn++) {
        s0 += v[nn][0]; q0 = fmaf(v[nn][0], v[nn][0], q0);
        s0 += v[nn][1]; q0 = fmaf(v[nn][1], v[nn][1], q0);
        s1 += v[nn][2]; q1 = fmaf(v[nn][2], v[nn][2], q1);
        s1 += v[nn][3]; q1 = fmaf(v[nn][3], v[nn][3], q1);
    }
#pragma unroll
    for (int msk = 1; msk <= 2; msk <<= 1) {
        s0 += __shfl_xor_sync(0xffffffffu, s0, msk);
        q0 += __shfl_xor_sync(0xffffffffu, q0, msk);
        s1 += __shfl_xor_sync(0xffffffffu, s1, msk);
        q1 += __shfl_xor_sync(0xffffffffu, q1, msk);
    }
    float mu0 = s0 * 0.015625f, mu1 = s1 * 0.015625f;
    float rs0 = rsqrtf(fmaf(-mu0, mu0, q0 * 0.015625f) + 1e-5f);
    float rs1 = rsqrtf(fmaf(-mu1, mu1, q1 * 0.015625f) + 1e-5f);
#pragma unroll
    for (int nn = 0; nn < 8; nn++) {
        float2 g2 = *(const float2*)(pG + nn * 8 + 2 * q);
        float2 h2 = *(const float2*)(pH + nn * 8 + 2 * q);
        v[nn][0] = fmaxf(fmaf((v[nn][0] - mu0) * rs0, g2.x, h2.x), 0.f);
        v[nn][1] = fmaxf(fmaf((v[nn][1] - mu0) * rs0, g2.y, h2.y), 0.f);
        v[nn][2] = fmaxf(fmaf((v[nn][2] - mu1) * rs1, g2.x, h2.x), 0.f);
        v[nn][3] = fmaxf(fmaf((v[nn][3] - mu1) * rs1, g2.y, h2.y), 0.f);
    }
}

__global__ void __launch_bounds__(128, 3) mlp_kernel(
    const float* __restrict__ x,
    const float* __restrict__ W0, const float* __restrict__ B0,
    const float* __restrict__ G0, const float* __restrict__ H0,
    const float* __restrict__ W1, const float* __restrict__ B1,
    const float* __restrict__ G1, const float* __restrict__ H1,
    const float* __restrict__ W2, const float* __restrict__ B2,
    const float* __restrict__ G2, const float* __restrict__ H2,
    const float* __restrict__ W3, const float* __restrict__ B3,
    const float* __restrict__ G3, const float* __restrict__ H3,
    const float* __restrict__ W4, const float* __restrict__ B4,
    float* __restrict__ out)
{
    extern __shared__ float sm[];
    const int tid = threadIdx.x;
    const int w = tid >> 5;
    const int lane = tid & 31;
    const int g = lane >> 2;
    const int q = lane & 3;
    const int m = blockIdx.y;
    const int cnt = g_counts[m];
    const int base = g_offsets[m];

    // ---- build fragment-ordered weights in SMEM ----
    {
        // layers 1..3: frag[l][(kk*8+nn)*32 + lane] = (W[n][k], W[n][k+4]) as tf32
        const float* Ws[3] = { W1 + m * 4096, W2 + m * 4096, W3 + m * 4096 };
        uint2* bf = (uint2*)(sm + OFF_BF);
        for (int l = 0; l < 3; l++) {
            const float* Wl = Ws[l];
            for (int j = tid; j < 2048; j += 128) {
                int ln = j & 31, nk = j >> 5;
                int kk = nk >> 3, nn = nk & 7;
                int n = nn * 8 + (ln >> 2);
                int k = kk * 8 + (ln & 3);
                bf[l * 2048 + j] = make_uint2(cvt_tf32(Wl[n * 64 + k]),
                                              cvt_tf32(Wl[n * 64 + k + 4]));
            }
        }
        // layer0 frags (K padded to 8; k==6 carries bias via constant-1 input)
        uint2* b0f = (uint2*)(sm + OFF_B0F);
        for (int j = tid; j < 256; j += 128) {
            int ln = j & 31, nn = j >> 5;
            int n = nn * 8 + (ln >> 2);
            int k = ln & 3;                       // b0: k in 0..3 (always valid)
            float v0 = W0[m * 384 + n * 6 + k];
            float v1 = (k < 2) ? W0[m * 384 + n * 6 + k + 4]
                     : (k == 2) ? B0[m * 64 + n] : 0.0f;   // k+4 = 6 -> bias, 7 -> 0
            b0f[j] = make_uint2(cvt_tf32(v0), cvt_tf32(v1));
        }
        if (tid < 64) {
            sm[OFF_GH0 + tid]       = G0[m * 64 + tid];
            sm[OFF_GH0 + 64 + tid]  = H0[m * 64 + tid];
            sm[OFF_BGH + tid]       = B1[m * 64 + tid];
            sm[OFF_BGH + 64 + tid]  = G1[m * 64 + tid];
            sm[OFF_BGH + 128 + tid] = H1[m * 64 + tid];
            sm[OFF_BGH + 192 + tid] = B2[m * 64 + tid];
            sm[OFF_BGH + 256 + tid] = G2[m * 64 + tid];
            sm[OFF_BGH + 320 + tid] = H2[m * 64 + tid];
            sm[OFF_BGH + 384 + tid] = B3[m * 64 + tid];
            sm[OFF_BGH + 448 + tid] = G3[m * 64 + tid];
            sm[OFF_BGH + 512 + tid] = H3[m * 64 + tid];
        }
        for (int i = tid; i < 192; i += 128) sm[OFF_W4 + i] = W4[m * 192 + i];
        if (tid < 3) sm[OFF_B4 + tid] = B4[m * 3 + tid];
    }
    __syncthreads();

    uint32_t* stg = (uint32_t*)(sm + OFF_STAGE);
    const uint2* b0f = (const uint2*)(sm + OFF_B0F);
    const uint2* bf  = (const uint2*)(sm + OFF_BF);

    for (int t0 = (int)blockIdx.x * 128; t0 < cnt; t0 += (int)gridDim.x * 128) {
        const int pos = t0 + tid;
        const int posc = min(pos, cnt - 1);
        const int smp = g_perm[base + posc];

        // stage this thread's sample (row tid), tf32 bits, K padded to 8
#pragma unroll
        for (int c = 0; c < 6; c++) stg[tid * 12 + c] = cvt_tf32(x[smp * 6 + c]);
        stg[tid * 12 + 6] = 0x3F800000u;   // bias lane (1.0f is exact tf32)
        stg[tid * 12 + 7] = 0u;
        __syncwarp();

#pragma unroll 1
        for (int mt = 0; mt < 2; mt++) {
            const int rbase = w * 32 + mt * 16;

            // ---- layer 0: one k-step mma (bias folded) ----
            float h[8][4];
            {
                uint32_t a[4];
                a[0] = stg[(rbase + g) * 12 + q];
                a[1] = stg[(rbase + g + 8) * 12 + q];
                a[2] = stg[(rbase + g) * 12 + q + 4];
                a[3] = stg[(rbase + g + 8) * 12 + q + 4];
#pragma unroll
                for (int nn = 0; nn < 8; nn++) {
                    h[nn][0] = h[nn][1] = h[nn][2] = h[nn][3] = 0.f;
                    uint2 b = b0f[nn * 32 + lane];
                    mma_tf32(h[nn], a, b.x, b.y);
                }
            }
            ln16(h, nullptr, sm + OFF_GH0, sm + OFF_GH0 + 64, q);

            // ---- layers 1..3 ----
            const int L0 = (lane & ~3) | (q >> 1);
            const int L1 = L0 + 2;
            const bool podd = (q & 1);
#pragma unroll 1
            for (int l = 0; l < 3; l++) {
                float dn[8][4];
#pragma unroll
                for (int nn = 0; nn < 8; nn++)
                    dn[nn][0] = dn[nn][1] = dn[nn][2] = dn[nn][3] = 0.f;
                const uint2* bl = bf + l * 2048;
#pragma unroll
                for (int kk = 0; kk < 8; kk++) {
                    float s00 = __shfl_sync(0xffffffffu, h[kk][0], L0);
                    float s01 = __shfl_sync(0xffffffffu, h[kk][1], L0);
                    float s02 = __shfl_sync(0xffffffffu, h[kk][2], L0);
                    float s03 = __shfl_sync(0xffffffffu, h[kk][3], L0);
                    float s10 = __shfl_sync(0xffffffffu, h[kk][0], L1);
                    float s11 = __shfl_sync(0xffffffffu, h[kk][1], L1);
                    float s12 = __shfl_sync(0xffffffffu, h[kk][2], L1);
                    float s13 = __shfl_sync(0xffffffffu, h[kk][3], L1);
                    uint32_t a[4];
                    a[0] = cvt_tf32(podd ? s01 : s00);
                    a[1] = cvt_tf32(podd ? s03 : s02);
                    a[2] = cvt_tf32(podd ? s11 : s10);
                    a[3] = cvt_tf32(podd ? s13 : s12);
#pragma unroll
                    for (int nn = 0; nn < 8; nn++) {
                        uint2 b = bl[(kk * 8 + nn) * 32 + lane];
                        mma_tf32(dn[nn], a, b.x, b.y);
                    }
                }
                const float* pB = sm + OFF_BGH + l * 192;
                ln16(dn, pB, pB + 64, pB + 128, q);
#pragma unroll
                for (int nn = 0; nn < 8; nn++) {
                    h[nn][0] = dn[nn][0]; h[nn][1] = dn[nn][1];
                    h[nn][2] = dn[nn][2]; h[nn][3] = dn[nn][3];
                }
            }

            // ---- head: 64 -> 3 ----
            float p00 = 0.f, p01 = 0.f, p02 = 0.f, p10 = 0.f, p11 = 0.f, p12 = 0.f;
#pragma unroll
            for (int nn = 0; nn < 8; nn++) {
                float2 w0 = *(const float2*)(sm + OFF_W4 + 0 * 64 + nn * 8 + 2 * q);
                float2 w1 = *(const float2*)(sm + OFF_W4 + 1 * 64 + nn * 8 + 2 * q);
                float2 w2 = *(const float2*)(sm + OFF_W4 + 2 * 64 + nn * 8 + 2 * q);
                p00 = fmaf(w0.x, h[nn][0], fmaf(w0.y, h[nn][1], p00));
                p10 = fmaf(w0.x, h[nn][2], fmaf(w0.y, h[nn][3], p10));
                p01 = fmaf(w1.x, h[nn][0], fmaf(w1.y, h[nn][1], p01));
                p11 = fmaf(w1.x, h[nn][2], fmaf(w1.y, h[nn][3], p11));
                p02 = fmaf(w2.x, h[nn][0], fmaf(w2.y, h[nn][1], p02));
                p12 = fmaf(w2.x, h[nn][2], fmaf(w2.y, h[nn][3], p12));
            }
#pragma unroll
            for (int msk = 1; msk <= 2; msk <<= 1) {
                p00 += __shfl_xor_sync(0xffffffffu, p00, msk);
                p01 += __shfl_xor_sync(0xffffffffu, p01, msk);
                p02 += __shfl_xor_sync(0xffffffffu, p02, msk);
                p10 += __shfl_xor_sync(0xffffffffu, p10, msk);
                p11 += __shfl_xor_sync(0xffffffffu, p11, msk);
                p12 += __shfl_xor_sync(0xffffffffu, p12, msk);
            }
            int s_r0 = __shfl_sync(0xffffffffu, smp, mt * 16 + g);
            int s_r1 = __shfl_sync(0xffffffffu, smp, mt * 16 + g + 8);
            int pos_r0 = t0 + rbase + g;
            if (q < 3) {
                float v0 = (q == 0) ? p00 : (q == 1) ? p01 : p02;
                float v1 = (q == 0) ? p10 : (q == 1) ? p11 : p12;
                float bq = sm[OFF_B4 + q];
                if (pos_r0 < cnt)     out[s_r0 * 3 + q] = v0 + bq;
                if (pos_r0 + 8 < cnt) out[s_r1 * 3 + q] = v1 + bq;
            }
        }
    }
}

// ---------------- launch -----------------------------------------------------
extern "C" void kernel_launch(void* const* d_in, const int* in_sizes, int n_in,
                              void* d_out, int out_size) {
    const float* x  = (const float*)d_in[0];
    const int* idx  = (const int*)d_in[1];
    const float* W0 = (const float*)d_in[2];
    const float* B0 = (const float*)d_in[3];
    const float* G0 = (const float*)d_in[4];
    const float* H0 = (const float*)d_in[5];
    const float* W1 = (const float*)d_in[6];
    const float* B1 = (const float*)d_in[7];
    const float* G1 = (const float*)d_in[8];
    const float* H1 = (const float*)d_in[9];
    const float* W2 = (const float*)d_in[10];
    const float* B2 = (const float*)d_in[11];
    const float* G2 = (const float*)d_in[12];
    const float* H2 = (const float*)d_in[13];
    const float* W3 = (const float*)d_in[14];
    const float* B3 = (const float*)d_in[15];
    const float* G3 = (const float*)d_in[16];
    const float* H3 = (const float*)d_in[17];
    const float* W4 = (const float*)d_in[18];
    const float* B4 = (const float*)d_in[19];
    float* out = (float*)d_out;

    int N = in_sizes[1];
    if (N > MAXN) N = MAXN;

    cudaFuncSetAttribute(mlp_kernel, cudaFuncAttributeMaxDynamicSharedMemorySize,
                         SMEM_FLOATS * (int)sizeof(float));

    zero_kernel<<<1, 64>>>();
    hist_kernel<<<256, 256>>>(idx, N);
    scan_kernel<<<1, 64>>>();
    scatter_kernel<<<256, 256>>>(idx, N);

    dim3 grid(7, 64);
    mlp_kernel<<<grid, 128, SMEM_FLOATS * (int)sizeof(float)>>>(
        x, W0, B0, G0, H0, W1, B1, G1, H1, W2, B2, G2, H2, W3, B3, G3, H3, W4, B4, out);
}

// round 5
// speedup vs baseline: 3.8406x; 1.1074x over previous
#include <cuda_runtime.h>
#include <cstdint>

#define NM 64
#define MAXN 262144

// ---------------- scratch ---------------------------------------------------
__device__ int g_counts[NM];
__device__ int g_offsets[NM];
__device__ int g_cursor[NM];
__device__ int g_perm[MAXN];

// ---------------- prep kernels ----------------------------------------------
__global__ void zero_kernel() {
    if (threadIdx.x < NM) g_counts[threadIdx.x] = 0;
}

__global__ void hist_kernel(const int* __restrict__ idx, int N) {
    __shared__ int lc[NM];
    if (threadIdx.x < NM) lc[threadIdx.x] = 0;
    __syncthreads();
    for (int i = blockIdx.x * blockDim.x + threadIdx.x; i < N; i += gridDim.x * blockDim.x)
        atomicAdd(&lc[idx[i]], 1);
    __syncthreads();
    if (threadIdx.x < NM) atomicAdd(&g_counts[threadIdx.x], lc[threadIdx.x]);
}

__global__ void scan_kernel() {
    __shared__ int s[NM];
    int t = threadIdx.x;
    s[t] = g_counts[t];
    __syncthreads();
    if (t == 0) {
        int acc = 0;
        for (int i = 0; i < NM; i++) { int c = s[i]; s[i] = acc; acc += c; }
    }
    __syncthreads();
    g_offsets[t] = s[t];
    g_cursor[t]  = s[t];
}

__global__ void scatter_kernel(const int* __restrict__ idx, int N) {
    __shared__ int lc[NM];
    __shared__ int lbase[NM];
    int t = threadIdx.x;
    int per = (N + gridDim.x - 1) / gridDim.x;
    int lo = blockIdx.x * per;
    int hi = min(lo + per, N);
    if (t < NM) lc[t] = 0;
    __syncthreads();
    for (int i = lo + t; i < hi; i += blockDim.x)
        atomicAdd(&lc[idx[i]], 1);
    __syncthreads();
    if (t < NM) { lbase[t] = atomicAdd(&g_cursor[t], lc[t]); lc[t] = 0; }
    __syncthreads();
    for (int i = lo + t; i < hi; i += blockDim.x) {
        int m = idx[i];
        int r = atomicAdd(&lc[m], 1);
        g_perm[lbase[m] + r] = i;
    }
}

// ---------------- mma helpers ------------------------------------------------
__device__ __forceinline__ uint32_t cvt_tf32(float f) {
    uint32_t u; asm("cvt.rna.tf32.f32 %0, %1;" : "=r"(u) : "f"(f)); return u;
}

__device__ __forceinline__ void mma_tf32(float* d, const uint32_t* a, uint32_t b0, uint32_t b1) {
    asm volatile(
        "mma.sync.aligned.m16n8k8.row.col.f32.tf32.tf32.f32 "
        "{%0,%1,%2,%3}, {%4,%5,%6,%7}, {%8,%9}, {%0,%1,%2,%3};"
        : "+f"(d[0]), "+f"(d[1]), "+f"(d[2]), "+f"(d[3])
        : "r"(a[0]), "r"(a[1]), "r"(a[2]), "r"(a[3]), "r"(b0), "r"(b1));
}

// ---------------- SMEM layout (floats) ---------------------------------------
#define OFF_STAGE 0        // 128 x 12 (tf32 bits of x, padded K=8, stride 12)
#define OFF_B0F   1536     // layer0 B frags: 8nn x 32 lanes x float2 = 512
#define OFF_BF    2048     // layers 1..3 B frags: 3 x 4096
#define OFF_GH0   14336    // G0|H0 (128)
#define OFF_BGH   14464    // layers 1..3: B|G|H (192 each) = 576
#define OFF_W4    15040    // 192
#define OFF_B4    15232    // 4
#define SMEM_FLOATS 15236

// LayerNorm + ReLU on one warp m-tile held as D fragments v[8][4].
// Thread lane = g*4+q holds rows {g, g+8}, cols {8nn+2q, 8nn+2q+1}.
__device__ __forceinline__ void ln16(float v[8][4], const float* pB,
                                     const float* pG, const float* pH, int q) {
    if (pB) {
#pragma unroll
        for (int nn = 0; nn < 8; nn++) {
            float2 bb = *(const float2*)(pB + nn * 8 + 2 * q);
            v[nn][0] += bb.x; v[nn][1] += bb.y;
            v[nn][2] += bb.x; v[nn][3] += bb.y;
        }
    }
    float s0 = 0.f, s1 = 0.f, q0 = 0.f, q1 = 0.f;
#pragma unroll
    for (int nn = 0; nn < 8; nn++) {
        s0 += v[nn][0]; q0 = fmaf(v[nn][0], v[nn][0], q0);
        s0 += v[nn][1]; q0 = fmaf(v[nn][1], v[nn][1], q0);
        s1 += v[nn][2]; q1 = fmaf(v[nn][2], v[nn][2], q1);
        s1 += v[nn][3]; q1 = fmaf(v[nn][3], v[nn][3], q1);
    }
#pragma unroll
    for (int msk = 1; msk <= 2; msk <<= 1) {
        s0 += __shfl_xor_sync(0xffffffffu, s0, msk);
        q0 += __shfl_xor_sync(0xffffffffu, q0, msk);
        s1 += __shfl_xor_sync(0xffffffffu, s1, msk);
        q1 += __shfl_xor_sync(0xffffffffu, q1, msk);
    }
    float mu0 = s0 * 0.015625f, mu1 = s1 * 0.015625f;
    float rs0 = rsqrtf(fmaf(-mu0, mu0, q0 * 0.015625f) + 1e-5f);
    float rs1 = rsqrtf(fmaf(-mu1, mu1, q1 * 0.015625f) + 1e-5f);
#pragma unroll
    for (int nn = 0; nn < 8; nn++) {
        float2 g2 = *(const float2*)(pG + nn * 8 + 2 * q);
        float2 h2 = *(const float2*)(pH + nn * 8 + 2 * q);
        v[nn][0] = fmaxf(fmaf((v[nn][0] - mu0) * rs0, g2.x, h2.x), 0.f);
        v[nn][1] = fmaxf(fmaf((v[nn][1] - mu0) * rs0, g2.y, h2.y), 0.f);
        v[nn][2] = fmaxf(fmaf((v[nn][2] - mu1) * rs1, g2.x, h2.x), 0.f);
        v[nn][3] = fmaxf(fmaf((v[nn][3] - mu1) * rs1, g2.y, h2.y), 0.f);
    }
}

__global__ void __launch_bounds__(128, 3) mlp_kernel(
    const float* __restrict__ x,
    const float* __restrict__ W0, const float* __restrict__ B0,
    const float* __restrict__ G0, const float* __restrict__ H0,
    const float* __restrict__ W1, const float* __restrict__ B1,
    const float* __restrict__ G1, const float* __restrict__ H1,
    const float* __restrict__ W2, const float* __restrict__ B2,
    const float* __restrict__ G2, const float* __restrict__ H2,
    const float* __restrict__ W3, const float* __restrict__ B3,
    const float* __restrict__ G3, const float* __restrict__ H3,
    const float* __restrict__ W4, const float* __restrict__ B4,
    float* __restrict__ out)
{
    extern __shared__ float sm[];
    const int tid = threadIdx.x;
    const int w = tid >> 5;
    const int lane = tid & 31;
    const int g = lane >> 2;
    const int q = lane & 3;
    const int m = blockIdx.y;
    const int cnt = g_counts[m];
    const int base = g_offsets[m];

    // ---- build fragment-ordered weights in SMEM ----
    {
        // layers 1..3, PERMUTED k-mapping so that D fragments feed A directly:
        // A k-slot q carries feature kk*8+2q; k-slot q+4 carries kk*8+2q+1.
        // So frag entry (kk,nn,lane): b0 = W[n][kk*8+2q], b1 = W[n][kk*8+2q+1].
        const float* Ws[3] = { W1 + m * 4096, W2 + m * 4096, W3 + m * 4096 };
        uint2* bf = (uint2*)(sm + OFF_BF);
        for (int l = 0; l < 3; l++) {
            const float* Wl = Ws[l];
            for (int j = tid; j < 2048; j += 128) {
                int ln = j & 31, nk = j >> 5;
                int kk = nk >> 3, nn = nk & 7;
                int n = nn * 8 + (ln >> 2);
                int k = kk * 8 + 2 * (ln & 3);
                float2 wv = *(const float2*)(Wl + n * 64 + k);
                bf[l * 2048 + j] = make_uint2(cvt_tf32(wv.x), cvt_tf32(wv.y));
            }
        }
        // layer0 frags (K padded to 8; k==6 carries bias via constant-1 input)
        // standard k-mapping (A comes from staged x, built in A layout directly)
        uint2* b0f = (uint2*)(sm + OFF_B0F);
        for (int j = tid; j < 256; j += 128) {
            int ln = j & 31, nn = j >> 5;
            int n = nn * 8 + (ln >> 2);
            int k = ln & 3;                       // b0: k in 0..3 (always valid)
            float v0 = W0[m * 384 + n * 6 + k];
            float v1 = (k < 2) ? W0[m * 384 + n * 6 + k + 4]
                     : (k == 2) ? B0[m * 64 + n] : 0.0f;   // k+4 = 6 -> bias, 7 -> 0
            b0f[j] = make_uint2(cvt_tf32(v0), cvt_tf32(v1));
        }
        if (tid < 64) {
            sm[OFF_GH0 + tid]       = G0[m * 64 + tid];
            sm[OFF_GH0 + 64 + tid]  = H0[m * 64 + tid];
            sm[OFF_BGH + tid]       = B1[m * 64 + tid];
            sm[OFF_BGH + 64 + tid]  = G1[m * 64 + tid];
            sm[OFF_BGH + 128 + tid] = H1[m * 64 + tid];
            sm[OFF_BGH + 192 + tid] = B2[m * 64 + tid];
            sm[OFF_BGH + 256 + tid] = G2[m * 64 + tid];
            sm[OFF_BGH + 320 + tid] = H2[m * 64 + tid];
            sm[OFF_BGH + 384 + tid] = B3[m * 64 + tid];
            sm[OFF_BGH + 448 + tid] = G3[m * 64 + tid];
            sm[OFF_BGH + 512 + tid] = H3[m * 64 + tid];
        }
        for (int i = tid; i < 192; i += 128) sm[OFF_W4 + i] = W4[m * 192 + i];
        if (tid < 3) sm[OFF_B4 + tid] = B4[m * 3 + tid];
    }
    __syncthreads();

    uint32_t* stg = (uint32_t*)(sm + OFF_STAGE);
    const uint2* b0f = (const uint2*)(sm + OFF_B0F);
    const uint2* bf  = (const uint2*)(sm + OFF_BF);

    for (int t0 = (int)blockIdx.x * 128; t0 < cnt; t0 += (int)gridDim.x * 128) {
        const int pos = t0 + tid;
        const int posc = min(pos, cnt - 1);
        const int smp = g_perm[base + posc];

        // stage this thread's sample (row tid), tf32 bits, K padded to 8
#pragma unroll
        for (int c = 0; c < 6; c++) stg[tid * 12 + c] = cvt_tf32(x[smp * 6 + c]);
        stg[tid * 12 + 6] = 0x3F800000u;   // bias lane (1.0f is exact tf32)
        stg[tid * 12 + 7] = 0u;
        __syncwarp();

#pragma unroll 1
        for (int mt = 0; mt < 2; mt++) {
            const int rbase = w * 32 + mt * 16;

            // ---- layer 0: one k-step mma (bias folded) ----
            float h[8][4];
            {
                uint32_t a[4];
                a[0] = stg[(rbase + g) * 12 + q];
                a[1] = stg[(rbase + g + 8) * 12 + q];
                a[2] = stg[(rbase + g) * 12 + q + 4];
                a[3] = stg[(rbase + g + 8) * 12 + q + 4];
#pragma unroll
                for (int nn = 0; nn < 8; nn++) {
                    h[nn][0] = h[nn][1] = h[nn][2] = h[nn][3] = 0.f;
                    uint2 b = b0f[nn * 32 + lane];
                    mma_tf32(h[nn], a, b.x, b.y);
                }
            }
            ln16(h, nullptr, sm + OFF_GH0, sm + OFF_GH0 + 64, q);

            // ---- layers 1..3: D feeds A directly (weights k-permuted) ----
#pragma unroll 1
            for (int l = 0; l < 3; l++) {
                float dn[8][4];
#pragma unroll
                for (int nn = 0; nn < 8; nn++)
                    dn[nn][0] = dn[nn][1] = dn[nn][2] = dn[nn][3] = 0.f;
                const uint2* bl = bf + l * 2048;
#pragma unroll
                for (int kk = 0; kk < 8; kk++) {
                    uint32_t a[4];
                    a[0] = cvt_tf32(h[kk][0]);   // (row g,   feat kk*8+2q)   -> k-slot q
                    a[1] = cvt_tf32(h[kk][2]);   // (row g+8, feat kk*8+2q)   -> k-slot q
                    a[2] = cvt_tf32(h[kk][1]);   // (row g,   feat kk*8+2q+1) -> k-slot q+4
                    a[3] = cvt_tf32(h[kk][3]);   // (row g+8, feat kk*8+2q+1) -> k-slot q+4
#pragma unroll
                    for (int nn = 0; nn < 8; nn++) {
                        uint2 b = bl[(kk * 8 + nn) * 32 + lane];
                        mma_tf32(dn[nn], a, b.x, b.y);
                    }
                }
                const float* pB = sm + OFF_BGH + l * 192;
                ln16(dn, pB, pB + 64, pB + 128, q);
#pragma unroll
                for (int nn = 0; nn < 8; nn++) {
                    h[nn][0] = dn[nn][0]; h[nn][1] = dn[nn][1];
                    h[nn][2] = dn[nn][2]; h[nn][3] = dn[nn][3];
                }
            }

            // ---- head: 64 -> 3 ----
            float p00 = 0.f, p01 = 0.f, p02 = 0.f, p10 = 0.f, p11 = 0.f, p12 = 0.f;
#pragma unroll
            for (int nn = 0; nn < 8; nn++) {
                float2 w0 = *(const float2*)(sm + OFF_W4 + 0 * 64 + nn * 8 + 2 * q);
                float2 w1 = *(const float2*)(sm + OFF_W4 + 1 * 64 + nn * 8 + 2 * q);
                float2 w2 = *(const float2*)(sm + OFF_W4 + 2 * 64 + nn * 8 + 2 * q);
                p00 = fmaf(w0.x, h[nn][0], fmaf(w0.y, h[nn][1], p00));
                p10 = fmaf(w0.x, h[nn][2], fmaf(w0.y, h[nn][3], p10));
                p01 = fmaf(w1.x, h[nn][0], fmaf(w1.y, h[nn][1], p01));
                p11 = fmaf(w1.x, h[nn][2], fmaf(w1.y, h[nn][3], p11));
                p02 = fmaf(w2.x, h[nn][0], fmaf(w2.y, h[nn][1], p02));
                p12 = fmaf(w2.x, h[nn][2], fmaf(w2.y, h[nn][3], p12));
            }
#pragma unroll
            for (int msk = 1; msk <= 2; msk <<= 1) {
                p00 += __shfl_xor_sync(0xffffffffu, p00, msk);
                p01 += __shfl_xor_sync(0xffffffffu, p01, msk);
                p02 += __shfl_xor_sync(0xffffffffu, p02, msk);
                p10 += __shfl_xor_sync(0xffffffffu, p10, msk);
                p11 += __shfl_xor_sync(0xffffffffu, p11, msk);
                p12 += __shfl_xor_sync(0xffffffffu, p12, msk);
            }
            int s_r0 = __shfl_sync(0xffffffffu, smp, mt * 16 + g);
            int s_r1 = __shfl_sync(0xffffffffu, smp, mt * 16 + g + 8);
            int pos_r0 = t0 + rbase + g;
            if (q < 3) {
                float v0 = (q == 0) ? p00 : (q == 1) ? p01 : p02;
                float v1 = (q == 0) ? p10 : (q == 1) ? p11 : p12;
                float bq = sm[OFF_B4 + q];
                if (pos_r0 < cnt)     out[s_r0 * 3 + q] = v0 + bq;
                if (pos_r0 + 8 < cnt) out[s_r1 * 3 + q] = v1 + bq;
            }
        }
    }
}

// ---------------- launch -----------------------------------------------------
extern "C" void kernel_launch(void* const* d_in, const int* in_sizes, int n_in,
                              void* d_out, int out_size) {
    const float* x  = (const float*)d_in[0];
    const int* idx  = (const int*)d_in[1];
    const float* W0 = (const float*)d_in[2];
    const float* B0 = (const float*)d_in[3];
    const float* G0 = (const float*)d_in[4];
    const float* H0 = (const float*)d_in[5];
    const float* W1 = (const float*)d_in[6];
    const float* B1 = (const float*)d_in[7];
    const float* G1 = (const float*)d_in[8];
    const float* H1 = (const float*)d_in[9];
    const float* W2 = (const float*)d_in[10];
    const float* B2 = (const float*)d_in[11];
    const float* G2 = (const float*)d_in[12];
    const float* H2 = (const float*)d_in[13];
    const float* W3 = (const float*)d_in[14];
    const float* B3 = (const float*)d_in[15];
    const float* G3 = (const float*)d_in[16];
    const float* H3 = (const float*)d_in[17];
    const float* W4 = (const float*)d_in[18];
    const float* B4 = (const float*)d_in[19];
    float* out = (float*)d_out;

    int N = in_sizes[1];
    if (N > MAXN) N = MAXN;

    cudaFuncSetAttribute(mlp_kernel, cudaFuncAttributeMaxDynamicSharedMemorySize,
                         SMEM_FLOATS * (int)sizeof(float));

    zero_kernel<<<1, 64>>>();
    hist_kernel<<<256, 256>>>(idx, N);
    scan_kernel<<<1, 64>>>();
    scatter_kernel<<<256, 256>>>(idx, N);

    dim3 grid(7, 64);
    mlp_kernel<<<grid, 128, SMEM_FLOATS * (int)sizeof(float)>>>(
        x, W0, B0, G0, H0, W1, B1, G1, H1, W2, B2, G2, H2, W3, B3, G3, H3, W4, B4, out);
}

// round 6
// speedup vs baseline: 3.9347x; 1.0245x over previous
#include <cuda_runtime.h>
#include <cstdint>

#define NM 64
#define MAXN 262144

// ---------------- scratch ---------------------------------------------------
__device__ int g_counts[NM];        // statically zero-init; re-zeroed by scan_kernel
__device__ int g_offsets[NM + 1];
__device__ int g_cursor[NM];
__device__ int g_perm[MAXN];

// ---------------- prep kernels ----------------------------------------------
__global__ void hist_kernel(const int* __restrict__ idx, int N) {
    __shared__ int lc[NM];
    if (threadIdx.x < NM) lc[threadIdx.x] = 0;
    __syncthreads();
    for (int i = blockIdx.x * blockDim.x + threadIdx.x; i < N; i += gridDim.x * blockDim.x)
        atomicAdd(&lc[idx[i]], 1);
    __syncthreads();
    if (threadIdx.x < NM) atomicAdd(&g_counts[threadIdx.x], lc[threadIdx.x]);
}

__global__ void scan_kernel() {
    __shared__ int s[NM];
    int t = threadIdx.x;
    s[t] = g_counts[t];
    __syncthreads();
    if (t == 0) {
        int acc = 0;
        for (int i = 0; i < NM; i++) { int c = s[i]; s[i] = acc; acc += c; }
        g_offsets[NM] = acc;
    }
    __syncthreads();
    g_offsets[t] = s[t];
    g_cursor[t]  = s[t];
    g_counts[t]  = 0;     // pre-zero for the next kernel_launch invocation
}

__global__ void scatter_kernel(const int* __restrict__ idx, int N) {
    __shared__ int lc[NM];
    __shared__ int lbase[NM];
    int t = threadIdx.x;
    int per = (N + gridDim.x - 1) / gridDim.x;
    int lo = blockIdx.x * per;
    int hi = min(lo + per, N);
    if (t < NM) lc[t] = 0;
    __syncthreads();
    for (int i = lo + t; i < hi; i += blockDim.x)
        atomicAdd(&lc[idx[i]], 1);
    __syncthreads();
    if (t < NM) { lbase[t] = atomicAdd(&g_cursor[t], lc[t]); lc[t] = 0; }
    __syncthreads();
    for (int i = lo + t; i < hi; i += blockDim.x) {
        int m = idx[i];
        int r = atomicAdd(&lc[m], 1);
        g_perm[lbase[m] + r] = i;
    }
}

// ---------------- mma helpers ------------------------------------------------
__device__ __forceinline__ uint32_t cvt_tf32(float f) {
    uint32_t u; asm("cvt.rna.tf32.f32 %0, %1;" : "=r"(u) : "f"(f)); return u;
}

__device__ __forceinline__ void mma_tf32(float* d, const uint32_t* a, uint32_t b0, uint32_t b1) {
    asm volatile(
        "mma.sync.aligned.m16n8k8.row.col.f32.tf32.tf32.f32 "
        "{%0,%1,%2,%3}, {%4,%5,%6,%7}, {%8,%9}, {%0,%1,%2,%3};"
        : "+f"(d[0]), "+f"(d[1]), "+f"(d[2]), "+f"(d[3])
        : "r"(a[0]), "r"(a[1]), "r"(a[2]), "r"(a[3]), "r"(b0), "r"(b1));
}

// ---------------- SMEM layout (floats) ---------------------------------------
#define OFF_STAGE 0        // 128 x 12 (tf32 bits of x, padded K=8, stride 12)
#define OFF_B0F   1536     // layer0 B frags: 8nn x 32 lanes x float2 = 512
#define OFF_BF    2048     // layers 1..3 B frags: 3 x 4096
#define OFF_GH0   14336    // G0|H0 (128)
#define OFF_BGH   14464    // layers 1..3: B|G|H (192 each) = 576
#define OFF_W4    15040    // 192
#define OFF_B4    15232    // 4
#define SMEM_FLOATS 15236

// LayerNorm + ReLU on one warp m-tile held as D fragments v[8][4].
// Thread lane = g*4+q holds rows {g, g+8}, cols {8nn+2q, 8nn+2q+1}.
__device__ __forceinline__ void ln16(float v[8][4], const float* pB,
                                     const float* pG, const float* pH, int q) {
    if (pB) {
#pragma unroll
        for (int nn = 0; nn < 8; nn++) {
            float2 bb = *(const float2*)(pB + nn * 8 + 2 * q);
            v[nn][0] += bb.x; v[nn][1] += bb.y;
            v[nn][2] += bb.x; v[nn][3] += bb.y;
        }
    }
    float s0 = 0.f, s1 = 0.f, q0 = 0.f, q1 = 0.f;
#pragma unroll
    for (int nn = 0; nn < 8; nn++) {
        s0 += v[nn][0]; q0 = fmaf(v[nn][0], v[nn][0], q0);
        s0 += v[nn][1]; q0 = fmaf(v[nn][1], v[nn][1], q0);
        s1 += v[nn][2]; q1 = fmaf(v[nn][2], v[nn][2], q1);
        s1 += v[nn][3]; q1 = fmaf(v[nn][3], v[nn][3], q1);
    }
#pragma unroll
    for (int msk = 1; msk <= 2; msk <<= 1) {
        s0 += __shfl_xor_sync(0xffffffffu, s0, msk);
        q0 += __shfl_xor_sync(0xffffffffu, q0, msk);
        s1 += __shfl_xor_sync(0xffffffffu, s1, msk);
        q1 += __shfl_xor_sync(0xffffffffu, q1, msk);
    }
    float mu0 = s0 * 0.015625f, mu1 = s1 * 0.015625f;
    float rs0 = rsqrtf(fmaf(-mu0, mu0, q0 * 0.015625f) + 1e-5f);
    float rs1 = rsqrtf(fmaf(-mu1, mu1, q1 * 0.015625f) + 1e-5f);
#pragma unroll
    for (int nn = 0; nn < 8; nn++) {
        float2 g2 = *(const float2*)(pG + nn * 8 + 2 * q);
        float2 h2 = *(const float2*)(pH + nn * 8 + 2 * q);
        v[nn][0] = fmaxf(fmaf((v[nn][0] - mu0) * rs0, g2.x, h2.x), 0.f);
        v[nn][1] = fmaxf(fmaf((v[nn][1] - mu0) * rs0, g2.y, h2.y), 0.f);
        v[nn][2] = fmaxf(fmaf((v[nn][2] - mu1) * rs1, g2.x, h2.x), 0.f);
        v[nn][3] = fmaxf(fmaf((v[nn][3] - mu1) * rs1, g2.y, h2.y), 0.f);
    }
}

// 444 blocks = one exact wave at 3 blocks/SM on 148 SMs.
// block b: model m = b % 64, chunk j = b / 64. Models 0..59 have 7 blocks, 60..63 have 6.
__global__ void __launch_bounds__(128, 3) mlp_kernel(
    const float* __restrict__ x,
    const float* __restrict__ W0, const float* __restrict__ B0,
    const float* __restrict__ G0, const float* __restrict__ H0,
    const float* __restrict__ W1, const float* __restrict__ B1,
    const float* __restrict__ G1, const float* __restrict__ H1,
    const float* __restrict__ W2, const float* __restrict__ B2,
    const float* __restrict__ G2, const float* __restrict__ H2,
    const float* __restrict__ W3, const float* __restrict__ B3,
    const float* __restrict__ G3, const float* __restrict__ H3,
    const float* __restrict__ W4, const float* __restrict__ B4,
    float* __restrict__ out)
{
    extern __shared__ float sm[];
    const int tid = threadIdx.x;
    const int w = tid >> 5;
    const int lane = tid & 31;
    const int g = lane >> 2;
    const int q = lane & 3;
    const int b = blockIdx.x;
    const int m = b & 63;
    const int j = b >> 6;
    const int nb = (m < 60) ? 7 : 6;
    const int base = g_offsets[m];
    const int cnt = g_offsets[m + 1] - base;
    if (j * 128 >= cnt) return;

    // ---- build fragment-ordered weights in SMEM ----
    {
        // layers 1..3, PERMUTED k-mapping so that D fragments feed A directly:
        // frag entry (kk,nn,lane): b0 = W[n][kk*8+2q], b1 = W[n][kk*8+2q+1].
        const float* Ws[3] = { W1 + m * 4096, W2 + m * 4096, W3 + m * 4096 };
        uint2* bf = (uint2*)(sm + OFF_BF);
        for (int l = 0; l < 3; l++) {
            const float* Wl = Ws[l];
            for (int jj = tid; jj < 2048; jj += 128) {
                int ln = jj & 31, nk = jj >> 5;
                int kk = nk >> 3, nn = nk & 7;
                int n = nn * 8 + (ln >> 2);
                int k = kk * 8 + 2 * (ln & 3);
                float2 wv = *(const float2*)(Wl + n * 64 + k);
                bf[l * 2048 + jj] = make_uint2(cvt_tf32(wv.x), cvt_tf32(wv.y));
            }
        }
        // layer0 frags (K padded to 8; k==6 carries bias via constant-1 input)
        uint2* b0f = (uint2*)(sm + OFF_B0F);
        for (int jj = tid; jj < 256; jj += 128) {
            int ln = jj & 31, nn = jj >> 5;
            int n = nn * 8 + (ln >> 2);
            int k = ln & 3;
            float v0 = W0[m * 384 + n * 6 + k];
            float v1 = (k < 2) ? W0[m * 384 + n * 6 + k + 4]
                     : (k == 2) ? B0[m * 64 + n] : 0.0f;
            b0f[jj] = make_uint2(cvt_tf32(v0), cvt_tf32(v1));
        }
        if (tid < 64) {
            sm[OFF_GH0 + tid]       = G0[m * 64 + tid];
            sm[OFF_GH0 + 64 + tid]  = H0[m * 64 + tid];
            sm[OFF_BGH + tid]       = B1[m * 64 + tid];
            sm[OFF_BGH + 64 + tid]  = G1[m * 64 + tid];
            sm[OFF_BGH + 128 + tid] = H1[m * 64 + tid];
            sm[OFF_BGH + 192 + tid] = B2[m * 64 + tid];
            sm[OFF_BGH + 256 + tid] = G2[m * 64 + tid];
            sm[OFF_BGH + 320 + tid] = H2[m * 64 + tid];
            sm[OFF_BGH + 384 + tid] = B3[m * 64 + tid];
            sm[OFF_BGH + 448 + tid] = G3[m * 64 + tid];
            sm[OFF_BGH + 512 + tid] = H3[m * 64 + tid];
        }
        for (int i = tid; i < 192; i += 128) sm[OFF_W4 + i] = W4[m * 192 + i];
        if (tid < 3) sm[OFF_B4 + tid] = B4[m * 3 + tid];
    }
    __syncthreads();

    uint32_t* stg = (uint32_t*)(sm + OFF_STAGE);
    const uint2* b0f = (const uint2*)(sm + OFF_B0F);
    const uint2* bf  = (const uint2*)(sm + OFF_BF);

    for (int t0 = j * 128; t0 < cnt; t0 += nb * 128) {
        const int pos = t0 + tid;
        const int posc = min(pos, cnt - 1);
        const int smp = g_perm[base + posc];

        // stage this thread's sample (row tid), tf32 bits, K padded to 8
#pragma unroll
        for (int c = 0; c < 6; c++) stg[tid * 12 + c] = cvt_tf32(x[smp * 6 + c]);
        stg[tid * 12 + 6] = 0x3F800000u;   // bias lane (1.0f exact in tf32)
        stg[tid * 12 + 7] = 0u;
        __syncwarp();

#pragma unroll 1
        for (int mt = 0; mt < 2; mt++) {
            const int rbase = w * 32 + mt * 16;

            // ---- layer 0: one k-step mma (bias folded) ----
            float h[8][4];
            {
                uint32_t a[4];
                a[0] = stg[(rbase + g) * 12 + q];
                a[1] = stg[(rbase + g + 8) * 12 + q];
                a[2] = stg[(rbase + g) * 12 + q + 4];
                a[3] = stg[(rbase + g + 8) * 12 + q + 4];
#pragma unroll
                for (int nn = 0; nn < 8; nn++) {
                    h[nn][0] = h[nn][1] = h[nn][2] = h[nn][3] = 0.f;
                    uint2 bb = b0f[nn * 32 + lane];
                    mma_tf32(h[nn], a, bb.x, bb.y);
                }
            }
            ln16(h, nullptr, sm + OFF_GH0, sm + OFF_GH0 + 64, q);

            // ---- layers 1..3: D feeds A directly (weights k-permuted) ----
#pragma unroll 1
            for (int l = 0; l < 3; l++) {
                float dn[8][4];
#pragma unroll
                for (int nn = 0; nn < 8; nn++)
                    dn[nn][0] = dn[nn][1] = dn[nn][2] = dn[nn][3] = 0.f;
                const uint2* bl = bf + l * 2048;
#pragma unroll
                for (int kk = 0; kk < 8; kk++) {
                    uint32_t a[4];
                    a[0] = cvt_tf32(h[kk][0]);
                    a[1] = cvt_tf32(h[kk][2]);
                    a[2] = cvt_tf32(h[kk][1]);
                    a[3] = cvt_tf32(h[kk][3]);
#pragma unroll
                    for (int nn = 0; nn < 8; nn++) {
                        uint2 bb = bl[(kk * 8 + nn) * 32 + lane];
                        mma_tf32(dn[nn], a, bb.x, bb.y);
                    }
                }
                const float* pB = sm + OFF_BGH + l * 192;
                ln16(dn, pB, pB + 64, pB + 128, q);
#pragma unroll
                for (int nn = 0; nn < 8; nn++) {
                    h[nn][0] = dn[nn][0]; h[nn][1] = dn[nn][1];
                    h[nn][2] = dn[nn][2]; h[nn][3] = dn[nn][3];
                }
            }

            // ---- head: 64 -> 3 ----
            float p00 = 0.f, p01 = 0.f, p02 = 0.f, p10 = 0.f, p11 = 0.f, p12 = 0.f;
#pragma unroll
            for (int nn = 0; nn < 8; nn++) {
                float2 w0 = *(const float2*)(sm + OFF_W4 + 0 * 64 + nn * 8 + 2 * q);
                float2 w1 = *(const float2*)(sm + OFF_W4 + 1 * 64 + nn * 8 + 2 * q);
                float2 w2 = *(const float2*)(sm + OFF_W4 + 2 * 64 + nn * 8 + 2 * q);
                p00 = fmaf(w0.x, h[nn][0], fmaf(w0.y, h[nn][1], p00));
                p10 = fmaf(w0.x, h[nn][2], fmaf(w0.y, h[nn][3], p10));
                p01 = fmaf(w1.x, h[nn][0], fmaf(w1.y, h[nn][1], p01));
                p11 = fmaf(w1.x, h[nn][2], fmaf(w1.y, h[nn][3], p11));
                p02 = fmaf(w2.x, h[nn][0], fmaf(w2.y, h[nn][1], p02));
                p12 = fmaf(w2.x, h[nn][2], fmaf(w2.y, h[nn][3], p12));
            }
#pragma unroll
            for (int msk = 1; msk <= 2; msk <<= 1) {
                p00 += __shfl_xor_sync(0xffffffffu, p00, msk);
                p01 += __shfl_xor_sync(0xffffffffu, p01, msk);
                p02 += __shfl_xor_sync(0xffffffffu, p02, msk);
                p10 += __shfl_xor_sync(0xffffffffu, p10, msk);
                p11 += __shfl_xor_sync(0xffffffffu, p11, msk);
                p12 += __shfl_xor_sync(0xffffffffu, p12, msk);
            }
            int s_r0 = __shfl_sync(0xffffffffu, smp, mt * 16 + g);
            int s_r1 = __shfl_sync(0xffffffffu, smp, mt * 16 + g + 8);
            int pos_r0 = t0 + rbase + g;
            if (q < 3) {
                float v0 = (q == 0) ? p00 : (q == 1) ? p01 : p02;
                float v1 = (q == 0) ? p10 : (q == 1) ? p11 : p12;
                float bq = sm[OFF_B4 + q];
                if (pos_r0 < cnt)     out[s_r0 * 3 + q] = v0 + bq;
                if (pos_r0 + 8 < cnt) out[s_r1 * 3 + q] = v1 + bq;
            }
        }
    }
}

// ---------------- launch -----------------------------------------------------
extern "C" void kernel_launch(void* const* d_in, const int* in_sizes, int n_in,
                              void* d_out, int out_size) {
    const float* x  = (const float*)d_in[0];
    const int* idx  = (const int*)d_in[1];
    const float* W0 = (const float*)d_in[2];
    const float* B0 = (const float*)d_in[3];
    const float* G0 = (const float*)d_in[4];
    const float* H0 = (const float*)d_in[5];
    const float* W1 = (const float*)d_in[6];
    const float* B1 = (const float*)d_in[7];
    const float* G1 = (const float*)d_in[8];
    const float* H1 = (const float*)d_in[9];
    const float* W2 = (const float*)d_in[10];
    const float* B2 = (const float*)d_in[11];
    const float* G2 = (const float*)d_in[12];
    const float* H2 = (const float*)d_in[13];
    const float* W3 = (const float*)d_in[14];
    const float* B3 = (const float*)d_in[15];
    const float* G3 = (const float*)d_in[16];
    const float* H3 = (const float*)d_in[17];
    const float* W4 = (const float*)d_in[18];
    const float* B4 = (const float*)d_in[19];
    float* out = (float*)d_out;

    int N = in_sizes[1];
    if (N > MAXN) N = MAXN;

    cudaFuncSetAttribute(mlp_kernel, cudaFuncAttributeMaxDynamicSharedMemorySize,
                         SMEM_FLOATS * (int)sizeof(float));

    hist_kernel<<<512, 256>>>(idx, N);
    scan_kernel<<<1, 64>>>();
    scatter_kernel<<<512, 256>>>(idx, N);

    mlp_kernel<<<444, 128, SMEM_FLOATS * (int)sizeof(float)>>>(
        x, W0, B0, G0, H0, W1, B1, G1, H1, W2, B2, G2, H2, W3, B3, G3, H3, W4, B4, out);
}

// round 7
// speedup vs baseline: 4.1770x; 1.0616x over previous
#include <cuda_runtime.h>
#include <cstdint>

#define NM 64
#define MAXN 262144

// ---------------- scratch ---------------------------------------------------
__device__ int g_counts[NM];        // statically zero-init; re-zeroed by scan_kernel
__device__ int g_offsets[NM + 1];
__device__ int g_cursor[NM];
__device__ int g_perm[MAXN];

// ---------------- prep kernels ----------------------------------------------
__global__ void hist_kernel(const int* __restrict__ idx, int N) {
    __shared__ int lc[NM];
    if (threadIdx.x < NM) lc[threadIdx.x] = 0;
    __syncthreads();
    for (int i = blockIdx.x * blockDim.x + threadIdx.x; i < N; i += gridDim.x * blockDim.x)
        atomicAdd(&lc[idx[i]], 1);
    __syncthreads();
    if (threadIdx.x < NM) atomicAdd(&g_counts[threadIdx.x], lc[threadIdx.x]);
}

__global__ void scan_kernel() {
    __shared__ int s[NM];
    int t = threadIdx.x;
    s[t] = g_counts[t];
    __syncthreads();
    if (t == 0) {
        int acc = 0;
        for (int i = 0; i < NM; i++) { int c = s[i]; s[i] = acc; acc += c; }
        g_offsets[NM] = acc;
    }
    __syncthreads();
    g_offsets[t] = s[t];
    g_cursor[t]  = s[t];
    g_counts[t]  = 0;     // pre-zero for the next kernel_launch invocation
}

__global__ void scatter_kernel(const int* __restrict__ idx, int N) {
    __shared__ int lc[NM];
    __shared__ int lbase[NM];
    int t = threadIdx.x;
    int per = (N + gridDim.x - 1) / gridDim.x;
    int lo = blockIdx.x * per;
    int hi = min(lo + per, N);
    if (t < NM) lc[t] = 0;
    __syncthreads();
    for (int i = lo + t; i < hi; i += blockDim.x)
        atomicAdd(&lc[idx[i]], 1);
    __syncthreads();
    if (t < NM) { lbase[t] = atomicAdd(&g_cursor[t], lc[t]); lc[t] = 0; }
    __syncthreads();
    for (int i = lo + t; i < hi; i += blockDim.x) {
        int m = idx[i];
        int r = atomicAdd(&lc[m], 1);
        g_perm[lbase[m] + r] = i;
    }
}

// ---------------- mma helpers ------------------------------------------------
__device__ __forceinline__ uint32_t cvt_tf32(float f) {
    uint32_t u; asm("cvt.rna.tf32.f32 %0, %1;" : "=r"(u) : "f"(f)); return u;
}

__device__ __forceinline__ void mma_tf32(float* d, const uint32_t* a, uint32_t b0, uint32_t b1) {
    asm volatile(
        "mma.sync.aligned.m16n8k8.row.col.f32.tf32.tf32.f32 "
        "{%0,%1,%2,%3}, {%4,%5,%6,%7}, {%8,%9}, {%0,%1,%2,%3};"
        : "+f"(d[0]), "+f"(d[1]), "+f"(d[2]), "+f"(d[3])
        : "r"(a[0]), "r"(a[1]), "r"(a[2]), "r"(a[3]), "r"(b0), "r"(b1));
}

// ---------------- SMEM layout (floats) ---------------------------------------
#define OFF_STAGE 0        // 128 x 12 (tf32 bits of x, padded K=8, stride 12)
#define OFF_B0F   1536     // layer0 B frags: 8nn x 32 lanes x float2 = 512
#define OFF_BF    2048     // layers 1..3 B frags: 3 x 4096
#define OFF_GH0   14336    // G0|H0 (128)
#define OFF_BGH   14464    // layers 1..3: B|G|H (192 each) = 576
#define OFF_W4    15040    // 192
#define OFF_B4    15232    // 4
#define SMEM_FLOATS 15236

// Fused LayerNorm + ReLU on TWO warp m-tiles (v = rows g/g+8 of tile0,
// u = rows g/g+8 of tile1). Loads each B/G/H float2 ONCE, applies to both.
__device__ __forceinline__ void ln16x2(float v[8][4], float u[8][4], const float* pB,
                                       const float* pG, const float* pH, int q) {
    if (pB) {
#pragma unroll
        for (int nn = 0; nn < 8; nn++) {
            float2 bb = *(const float2*)(pB + nn * 8 + 2 * q);
            v[nn][0] += bb.x; v[nn][1] += bb.y; v[nn][2] += bb.x; v[nn][3] += bb.y;
            u[nn][0] += bb.x; u[nn][1] += bb.y; u[nn][2] += bb.x; u[nn][3] += bb.y;
        }
    }
    float vs0 = 0.f, vs1 = 0.f, vq0 = 0.f, vq1 = 0.f;
    float us0 = 0.f, us1 = 0.f, uq0 = 0.f, uq1 = 0.f;
#pragma unroll
    for (int nn = 0; nn < 8; nn++) {
        vs0 += v[nn][0]; vq0 = fmaf(v[nn][0], v[nn][0], vq0);
        vs0 += v[nn][1]; vq0 = fmaf(v[nn][1], v[nn][1], vq0);
        vs1 += v[nn][2]; vq1 = fmaf(v[nn][2], v[nn][2], vq1);
        vs1 += v[nn][3]; vq1 = fmaf(v[nn][3], v[nn][3], vq1);
        us0 += u[nn][0]; uq0 = fmaf(u[nn][0], u[nn][0], uq0);
        us0 += u[nn][1]; uq0 = fmaf(u[nn][1], u[nn][1], uq0);
        us1 += u[nn][2]; uq1 = fmaf(u[nn][2], u[nn][2], uq1);
        us1 += u[nn][3]; uq1 = fmaf(u[nn][3], u[nn][3], uq1);
    }
#pragma unroll
    for (int msk = 1; msk <= 2; msk <<= 1) {
        vs0 += __shfl_xor_sync(0xffffffffu, vs0, msk);
        vq0 += __shfl_xor_sync(0xffffffffu, vq0, msk);
        vs1 += __shfl_xor_sync(0xffffffffu, vs1, msk);
        vq1 += __shfl_xor_sync(0xffffffffu, vq1, msk);
        us0 += __shfl_xor_sync(0xffffffffu, us0, msk);
        uq0 += __shfl_xor_sync(0xffffffffu, uq0, msk);
        us1 += __shfl_xor_sync(0xffffffffu, us1, msk);
        uq1 += __shfl_xor_sync(0xffffffffu, uq1, msk);
    }
    float vmu0 = vs0 * 0.015625f, vmu1 = vs1 * 0.015625f;
    float umu0 = us0 * 0.015625f, umu1 = us1 * 0.015625f;
    float vrs0 = rsqrtf(fmaf(-vmu0, vmu0, vq0 * 0.015625f) + 1e-5f);
    float vrs1 = rsqrtf(fmaf(-vmu1, vmu1, vq1 * 0.015625f) + 1e-5f);
    float urs0 = rsqrtf(fmaf(-umu0, umu0, uq0 * 0.015625f) + 1e-5f);
    float urs1 = rsqrtf(fmaf(-umu1, umu1, uq1 * 0.015625f) + 1e-5f);
#pragma unroll
    for (int nn = 0; nn < 8; nn++) {
        float2 g2 = *(const float2*)(pG + nn * 8 + 2 * q);
        float2 h2 = *(const float2*)(pH + nn * 8 + 2 * q);
        v[nn][0] = fmaxf(fmaf((v[nn][0] - vmu0) * vrs0, g2.x, h2.x), 0.f);
        v[nn][1] = fmaxf(fmaf((v[nn][1] - vmu0) * vrs0, g2.y, h2.y), 0.f);
        v[nn][2] = fmaxf(fmaf((v[nn][2] - vmu1) * vrs1, g2.x, h2.x), 0.f);
        v[nn][3] = fmaxf(fmaf((v[nn][3] - vmu1) * vrs1, g2.y, h2.y), 0.f);
        u[nn][0] = fmaxf(fmaf((u[nn][0] - umu0) * urs0, g2.x, h2.x), 0.f);
        u[nn][1] = fmaxf(fmaf((u[nn][1] - umu0) * urs0, g2.y, h2.y), 0.f);
        u[nn][2] = fmaxf(fmaf((u[nn][2] - umu1) * urs1, g2.x, h2.x), 0.f);
        u[nn][3] = fmaxf(fmaf((u[nn][3] - umu1) * urs1, g2.y, h2.y), 0.f);
    }
}

// 444 blocks = one exact wave at 3 blocks/SM on 148 SMs.
// block b: model m = b % 64, chunk j = b / 64. Models 0..59 have 7 blocks, 60..63 have 6.
__global__ void __launch_bounds__(128, 3) mlp_kernel(
    const float* __restrict__ x,
    const float* __restrict__ W0, const float* __restrict__ B0,
    const float* __restrict__ G0, const float* __restrict__ H0,
    const float* __restrict__ W1, const float* __restrict__ B1,
    const float* __restrict__ G1, const float* __restrict__ H1,
    const float* __restrict__ W2, const float* __restrict__ B2,
    const float* __restrict__ G2, const float* __restrict__ H2,
    const float* __restrict__ W3, const float* __restrict__ B3,
    const float* __restrict__ G3, const float* __restrict__ H3,
    const float* __restrict__ W4, const float* __restrict__ B4,
    float* __restrict__ out)
{
    extern __shared__ float sm[];
    const int tid = threadIdx.x;
    const int w = tid >> 5;
    const int lane = tid & 31;
    const int g = lane >> 2;
    const int q = lane & 3;
    const int b = blockIdx.x;
    const int m = b & 63;
    const int j = b >> 6;
    const int nb = (m < 60) ? 7 : 6;
    const int base = g_offsets[m];
    const int cnt = g_offsets[m + 1] - base;
    if (j * 128 >= cnt) return;

    // ---- build fragment-ordered weights in SMEM ----
    {
        // layers 1..3, PERMUTED k-mapping so that D fragments feed A directly:
        // frag entry (kk,nn,lane): b0 = W[n][kk*8+2q], b1 = W[n][kk*8+2q+1].
        const float* Ws[3] = { W1 + m * 4096, W2 + m * 4096, W3 + m * 4096 };
        uint2* bf = (uint2*)(sm + OFF_BF);
        for (int l = 0; l < 3; l++) {
            const float* Wl = Ws[l];
            for (int jj = tid; jj < 2048; jj += 128) {
                int ln = jj & 31, nk = jj >> 5;
                int kk = nk >> 3, nn = nk & 7;
                int n = nn * 8 + (ln >> 2);
                int k = kk * 8 + 2 * (ln & 3);
                float2 wv = *(const float2*)(Wl + n * 64 + k);
                bf[l * 2048 + jj] = make_uint2(cvt_tf32(wv.x), cvt_tf32(wv.y));
            }
        }
        // layer0 frags (K padded to 8; k==6 carries bias via constant-1 input)
        uint2* b0f = (uint2*)(sm + OFF_B0F);
        for (int jj = tid; jj < 256; jj += 128) {
            int ln = jj & 31, nn = jj >> 5;
            int n = nn * 8 + (ln >> 2);
            int k = ln & 3;
            float v0 = W0[m * 384 + n * 6 + k];
            float v1 = (k < 2) ? W0[m * 384 + n * 6 + k + 4]
                     : (k == 2) ? B0[m * 64 + n] : 0.0f;
            b0f[jj] = make_uint2(cvt_tf32(v0), cvt_tf32(v1));
        }
        if (tid < 64) {
            sm[OFF_GH0 + tid]       = G0[m * 64 + tid];
            sm[OFF_GH0 + 64 + tid]  = H0[m * 64 + tid];
            sm[OFF_BGH + tid]       = B1[m * 64 + tid];
            sm[OFF_BGH + 64 + tid]  = G1[m * 64 + tid];
            sm[OFF_BGH + 128 + tid] = H1[m * 64 + tid];
            sm[OFF_BGH + 192 + tid] = B2[m * 64 + tid];
            sm[OFF_BGH + 256 + tid] = G2[m * 64 + tid];
            sm[OFF_BGH + 320 + tid] = H2[m * 64 + tid];
            sm[OFF_BGH + 384 + tid] = B3[m * 64 + tid];
            sm[OFF_BGH + 448 + tid] = G3[m * 64 + tid];
            sm[OFF_BGH + 512 + tid] = H3[m * 64 + tid];
        }
        for (int i = tid; i < 192; i += 128) sm[OFF_W4 + i] = W4[m * 192 + i];
        if (tid < 3) sm[OFF_B4 + tid] = B4[m * 3 + tid];
    }
    __syncthreads();

    uint32_t* stg = (uint32_t*)(sm + OFF_STAGE);
    const uint2* b0f = (const uint2*)(sm + OFF_B0F);
    const uint2* bf  = (const uint2*)(sm + OFF_BF);
    const int rbase = w * 32;

    for (int t0 = j * 128; t0 < cnt; t0 += nb * 128) {
        const int pos = t0 + tid;
        const int posc = min(pos, cnt - 1);
        const int smp = g_perm[base + posc];

        // stage this thread's sample (row tid), tf32 bits, K padded to 8
#pragma unroll
        for (int c = 0; c < 6; c++) stg[tid * 12 + c] = cvt_tf32(x[smp * 6 + c]);
        stg[tid * 12 + 6] = 0x3F800000u;   // bias lane (1.0f exact in tf32)
        stg[tid * 12 + 7] = 0u;
        __syncwarp();

        // ---- layer 0: both m-tiles, each B frag loaded once ----
        float h0[8][4], h1[8][4];
        {
            uint32_t a0[4], a1[4];
            a0[0] = stg[(rbase + g) * 12 + q];
            a0[1] = stg[(rbase + g + 8) * 12 + q];
            a0[2] = stg[(rbase + g) * 12 + q + 4];
            a0[3] = stg[(rbase + g + 8) * 12 + q + 4];
            a1[0] = stg[(rbase + 16 + g) * 12 + q];
            a1[1] = stg[(rbase + 24 + g) * 12 + q];
            a1[2] = stg[(rbase + 16 + g) * 12 + q + 4];
            a1[3] = stg[(rbase + 24 + g) * 12 + q + 4];
#pragma unroll
            for (int nn = 0; nn < 8; nn++) {
                h0[nn][0] = h0[nn][1] = h0[nn][2] = h0[nn][3] = 0.f;
                h1[nn][0] = h1[nn][1] = h1[nn][2] = h1[nn][3] = 0.f;
                uint2 bb = b0f[nn * 32 + lane];
                mma_tf32(h0[nn], a0, bb.x, bb.y);
                mma_tf32(h1[nn], a1, bb.x, bb.y);
            }
        }
        ln16x2(h0, h1, nullptr, sm + OFF_GH0, sm + OFF_GH0 + 64, q);

        // ---- layers 1..3: D feeds A directly (weights k-permuted) ----
#pragma unroll 1
        for (int l = 0; l < 3; l++) {
            float d0[8][4], d1[8][4];
#pragma unroll
            for (int nn = 0; nn < 8; nn++) {
                d0[nn][0] = d0[nn][1] = d0[nn][2] = d0[nn][3] = 0.f;
                d1[nn][0] = d1[nn][1] = d1[nn][2] = d1[nn][3] = 0.f;
            }
            const uint2* bl = bf + l * 2048 + lane;
#pragma unroll
            for (int kk = 0; kk < 8; kk++) {
                uint32_t a0[4], a1[4];
                a0[0] = cvt_tf32(h0[kk][0]);
                a0[1] = cvt_tf32(h0[kk][2]);
                a0[2] = cvt_tf32(h0[kk][1]);
                a0[3] = cvt_tf32(h0[kk][3]);
                a1[0] = cvt_tf32(h1[kk][0]);
                a1[1] = cvt_tf32(h1[kk][2]);
                a1[2] = cvt_tf32(h1[kk][1]);
                a1[3] = cvt_tf32(h1[kk][3]);
#pragma unroll
                for (int nn = 0; nn < 8; nn++) {
                    uint2 bb = bl[(kk * 8 + nn) * 32];
                    mma_tf32(d0[nn], a0, bb.x, bb.y);
                    mma_tf32(d1[nn], a1, bb.x, bb.y);
                }
            }
            const float* pB = sm + OFF_BGH + l * 192;
            ln16x2(d0, d1, pB, pB + 64, pB + 128, q);
#pragma unroll
            for (int nn = 0; nn < 8; nn++) {
                h0[nn][0] = d0[nn][0]; h0[nn][1] = d0[nn][1];
                h0[nn][2] = d0[nn][2]; h0[nn][3] = d0[nn][3];
                h1[nn][0] = d1[nn][0]; h1[nn][1] = d1[nn][1];
                h1[nn][2] = d1[nn][2]; h1[nn][3] = d1[nn][3];
            }
        }

        // ---- head: 64 -> 3, both tiles, W4 loaded once ----
        float p000 = 0.f, p001 = 0.f, p002 = 0.f, p010 = 0.f, p011 = 0.f, p012 = 0.f;
        float p100 = 0.f, p101 = 0.f, p102 = 0.f, p110 = 0.f, p111 = 0.f, p112 = 0.f;
#pragma unroll
        for (int nn = 0; nn < 8; nn++) {
            float2 w0 = *(const float2*)(sm + OFF_W4 + 0 * 64 + nn * 8 + 2 * q);
            float2 w1 = *(const float2*)(sm + OFF_W4 + 1 * 64 + nn * 8 + 2 * q);
            float2 w2 = *(const float2*)(sm + OFF_W4 + 2 * 64 + nn * 8 + 2 * q);
            p000 = fmaf(w0.x, h0[nn][0], fmaf(w0.y, h0[nn][1], p000));
            p010 = fmaf(w0.x, h0[nn][2], fmaf(w0.y, h0[nn][3], p010));
            p001 = fmaf(w1.x, h0[nn][0], fmaf(w1.y, h0[nn][1], p001));
            p011 = fmaf(w1.x, h0[nn][2], fmaf(w1.y, h0[nn][3], p011));
            p002 = fmaf(w2.x, h0[nn][0], fmaf(w2.y, h0[nn][1], p002));
            p012 = fmaf(w2.x, h0[nn][2], fmaf(w2.y, h0[nn][3], p012));
            p100 = fmaf(w0.x, h1[nn][0], fmaf(w0.y, h1[nn][1], p100));
            p110 = fmaf(w0.x, h1[nn][2], fmaf(w0.y, h1[nn][3], p110));
            p101 = fmaf(w1.x, h1[nn][0], fmaf(w1.y, h1[nn][1], p101));
            p111 = fmaf(w1.x, h1[nn][2], fmaf(w1.y, h1[nn][3], p111));
            p102 = fmaf(w2.x, h1[nn][0], fmaf(w2.y, h1[nn][1], p102));
            p112 = fmaf(w2.x, h1[nn][2], fmaf(w2.y, h1[nn][3], p112));
        }
#pragma unroll
        for (int msk = 1; msk <= 2; msk <<= 1) {
            p000 += __shfl_xor_sync(0xffffffffu, p000, msk);
            p001 += __shfl_xor_sync(0xffffffffu, p001, msk);
            p002 += __shfl_xor_sync(0xffffffffu, p002, msk);
            p010 += __shfl_xor_sync(0xffffffffu, p010, msk);
            p011 += __shfl_xor_sync(0xffffffffu, p011, msk);
            p012 += __shfl_xor_sync(0xffffffffu, p012, msk);
            p100 += __shfl_xor_sync(0xffffffffu, p100, msk);
            p101 += __shfl_xor_sync(0xffffffffu, p101, msk);
            p102 += __shfl_xor_sync(0xffffffffu, p102, msk);
            p110 += __shfl_xor_sync(0xffffffffu, p110, msk);
            p111 += __shfl_xor_sync(0xffffffffu, p111, msk);
            p112 += __shfl_xor_sync(0xffffffffu, p112, msk);
        }
        int s_r0 = __shfl_sync(0xffffffffu, smp, g);
        int s_r1 = __shfl_sync(0xffffffffu, smp, g + 8);
        int s_r2 = __shfl_sync(0xffffffffu, smp, 16 + g);
        int s_r3 = __shfl_sync(0xffffffffu, smp, 24 + g);
        int pr = t0 + rbase + g;
        if (q < 3) {
            float v0 = (q == 0) ? p000 : (q == 1) ? p001 : p002;
            float v1 = (q == 0) ? p010 : (q == 1) ? p011 : p012;
            float v2 = (q == 0) ? p100 : (q == 1) ? p101 : p102;
            float v3 = (q == 0) ? p110 : (q == 1) ? p111 : p112;
            float bq = sm[OFF_B4 + q];
            if (pr < cnt)      out[s_r0 * 3 + q] = v0 + bq;
            if (pr + 8 < cnt)  out[s_r1 * 3 + q] = v1 + bq;
            if (pr + 16 < cnt) out[s_r2 * 3 + q] = v2 + bq;
            if (pr + 24 < cnt) out[s_r3 * 3 + q] = v3 + bq;
        }
    }
}

// ---------------- launch -----------------------------------------------------
extern "C" void kernel_launch(void* const* d_in, const int* in_sizes, int n_in,
                              void* d_out, int out_size) {
    const float* x  = (const float*)d_in[0];
    const int* idx  = (const int*)d_in[1];
    const float* W0 = (const float*)d_in[2];
    const float* B0 = (const float*)d_in[3];
    const float* G0 = (const float*)d_in[4];
    const float* H0 = (const float*)d_in[5];
    const float* W1 = (const float*)d_in[6];
    const float* B1 = (const float*)d_in[7];
    const float* G1 = (const float*)d_in[8];
    const float* H1 = (const float*)d_in[9];
    const float* W2 = (const float*)d_in[10];
    const float* B2 = (const float*)d_in[11];
    const float* G2 = (const float*)d_in[12];
    const float* H2 = (const float*)d_in[13];
    const float* W3 = (const float*)d_in[14];
    const float* B3 = (const float*)d_in[15];
    const float* G3 = (const float*)d_in[16];
    const float* H3 = (const float*)d_in[17];
    const float* W4 = (const float*)d_in[18];
    const float* B4 = (const float*)d_in[19];
    float* out = (float*)d_out;

    int N = in_sizes[1];
    if (N > MAXN) N = MAXN;

    cudaFuncSetAttribute(mlp_kernel, cudaFuncAttributeMaxDynamicSharedMemorySize,
                         SMEM_FLOATS * (int)sizeof(float));

    hist_kernel<<<512, 256>>>(idx, N);
    scan_kernel<<<1, 64>>>();
    scatter_kernel<<<512, 256>>>(idx, N);

    mlp_kernel<<<444, 128, SMEM_FLOATS * (int)sizeof(float)>>>(
        x, W0, B0, G0, H0, W1, B1, G1, H1, W2, B2, G2, H2, W3, B3, G3, H3, W4, B4, out);
}

// round 8
// speedup vs baseline: 5.4242x; 1.2986x over previous
#include <cuda_runtime.h>
#include <cstdint>

#define NM 64
#define MAXN 262144

// ---------------- scratch ---------------------------------------------------
__device__ int g_counts[NM];        // statically zero-init; re-zeroed by scan_kernel
__device__ int g_offsets[NM + 1];
__device__ int g_cursor[NM];
__device__ int g_perm[MAXN];

// ---------------- prep kernels ----------------------------------------------
__global__ void hist_kernel(const int* __restrict__ idx, int N) {
    __shared__ int lc[NM];
    if (threadIdx.x < NM) lc[threadIdx.x] = 0;
    __syncthreads();
    for (int i = blockIdx.x * blockDim.x + threadIdx.x; i < N; i += gridDim.x * blockDim.x)
        atomicAdd(&lc[idx[i]], 1);
    __syncthreads();
    if (threadIdx.x < NM) atomicAdd(&g_counts[threadIdx.x], lc[threadIdx.x]);
}

__global__ void scan_kernel() {
    __shared__ int s[NM];
    int t = threadIdx.x;
    s[t] = g_counts[t];
    __syncthreads();
    if (t == 0) {
        int acc = 0;
        for (int i = 0; i < NM; i++) { int c = s[i]; s[i] = acc; acc += c; }
        g_offsets[NM] = acc;
    }
    __syncthreads();
    g_offsets[t] = s[t];
    g_cursor[t]  = s[t];
    g_counts[t]  = 0;     // pre-zero for the next kernel_launch invocation
}

__global__ void scatter_kernel(const int* __restrict__ idx, int N) {
    __shared__ int lc[NM];
    __shared__ int lbase[NM];
    int t = threadIdx.x;
    int per = (N + gridDim.x - 1) / gridDim.x;
    int lo = blockIdx.x * per;
    int hi = min(lo + per, N);
    if (t < NM) lc[t] = 0;
    __syncthreads();
    for (int i = lo + t; i < hi; i += blockDim.x)
        atomicAdd(&lc[idx[i]], 1);
    __syncthreads();
    if (t < NM) { lbase[t] = atomicAdd(&g_cursor[t], lc[t]); lc[t] = 0; }
    __syncthreads();
    for (int i = lo + t; i < hi; i += blockDim.x) {
        int m = idx[i];
        int r = atomicAdd(&lc[m], 1);
        g_perm[lbase[m] + r] = i;
    }
}

// ---------------- mma helpers ------------------------------------------------
// pack two f32 into f16x2: lo in low half, hi in high half
__device__ __forceinline__ uint32_t packh2(float lo, float hi) {
    uint32_t u;
    asm("cvt.rn.f16x2.f32 %0, %1, %2;" : "=r"(u) : "f"(hi), "f"(lo));
    return u;
}

__device__ __forceinline__ void mma_f16_k8(float* d, uint32_t a0, uint32_t a1, uint32_t b0) {
    asm volatile(
        "mma.sync.aligned.m16n8k8.row.col.f32.f16.f16.f32 "
        "{%0,%1,%2,%3}, {%4,%5}, {%6}, {%0,%1,%2,%3};"
        : "+f"(d[0]), "+f"(d[1]), "+f"(d[2]), "+f"(d[3])
        : "r"(a0), "r"(a1), "r"(b0));
}

__device__ __forceinline__ void mma_f16_k16(float* d, uint32_t a0, uint32_t a1,
                                            uint32_t a2, uint32_t a3,
                                            uint32_t b0, uint32_t b1) {
    asm volatile(
        "mma.sync.aligned.m16n8k16.row.col.f32.f16.f16.f32 "
        "{%0,%1,%2,%3}, {%4,%5,%6,%7}, {%8,%9}, {%0,%1,%2,%3};"
        : "+f"(d[0]), "+f"(d[1]), "+f"(d[2]), "+f"(d[3])
        : "r"(a0), "r"(a1), "r"(a2), "r"(a3), "r"(b0), "r"(b1));
}

// ---------------- SMEM layout (floats) ---------------------------------------
#define OFF_STAGE 0        // 128 rows x 4 uints (x as f16x2, K padded to 8)
#define OFF_B0F   512      // layer0 B frags: 8nn x 32 lanes x uint = 256
#define OFF_BF    768      // layers 1..3 B frags: 3 x (4kk*8nn*32 lanes) uint2 = 3 x 2048 fl
#define OFF_GH0   6912     // G0|H0 (128)
#define OFF_BGH   7040     // layers 1..3: B|G|H (192 each) = 576
#define OFF_W4    7616     // 192
#define OFF_B4    7808     // 4
#define SMEM_FLOATS 7812

// Fused LayerNorm + ReLU on TWO warp m-tiles (v = rows g/g+8 of tile0,
// u = rows g/g+8 of tile1). Loads each B/G/H float2 ONCE, applies to both.
__device__ __forceinline__ void ln16x2(float v[8][4], float u[8][4], const float* pB,
                                       const float* pG, const float* pH, int q) {
    if (pB) {
#pragma unroll
        for (int nn = 0; nn < 8; nn++) {
            float2 bb = *(const float2*)(pB + nn * 8 + 2 * q);
            v[nn][0] += bb.x; v[nn][1] += bb.y; v[nn][2] += bb.x; v[nn][3] += bb.y;
            u[nn][0] += bb.x; u[nn][1] += bb.y; u[nn][2] += bb.x; u[nn][3] += bb.y;
        }
    }
    float vs0 = 0.f, vs1 = 0.f, vq0 = 0.f, vq1 = 0.f;
    float us0 = 0.f, us1 = 0.f, uq0 = 0.f, uq1 = 0.f;
#pragma unroll
    for (int nn = 0; nn < 8; nn++) {
        vs0 += v[nn][0]; vq0 = fmaf(v[nn][0], v[nn][0], vq0);
        vs0 += v[nn][1]; vq0 = fmaf(v[nn][1], v[nn][1], vq0);
        vs1 += v[nn][2]; vq1 = fmaf(v[nn][2], v[nn][2], vq1);
        vs1 += v[nn][3]; vq1 = fmaf(v[nn][3], v[nn][3], vq1);
        us0 += u[nn][0]; uq0 = fmaf(u[nn][0], u[nn][0], uq0);
        us0 += u[nn][1]; uq0 = fmaf(u[nn][1], u[nn][1], uq0);
        us1 += u[nn][2]; uq1 = fmaf(u[nn][2], u[nn][2], uq1);
        us1 += u[nn][3]; uq1 = fmaf(u[nn][3], u[nn][3], uq1);
    }
#pragma unroll
    for (int msk = 1; msk <= 2; msk <<= 1) {
        vs0 += __shfl_xor_sync(0xffffffffu, vs0, msk);
        vq0 += __shfl_xor_sync(0xffffffffu, vq0, msk);
        vs1 += __shfl_xor_sync(0xffffffffu, vs1, msk);
        vq1 += __shfl_xor_sync(0xffffffffu, vq1, msk);
        us0 += __shfl_xor_sync(0xffffffffu, us0, msk);
        uq0 += __shfl_xor_sync(0xffffffffu, uq0, msk);
        us1 += __shfl_xor_sync(0xffffffffu, us1, msk);
        uq1 += __shfl_xor_sync(0xffffffffu, uq1, msk);
    }
    float vmu0 = vs0 * 0.015625f, vmu1 = vs1 * 0.015625f;
    float umu0 = us0 * 0.015625f, umu1 = us1 * 0.015625f;
    float vrs0 = rsqrtf(fmaf(-vmu0, vmu0, vq0 * 0.015625f) + 1e-5f);
    float vrs1 = rsqrtf(fmaf(-vmu1, vmu1, vq1 * 0.015625f) + 1e-5f);
    float urs0 = rsqrtf(fmaf(-umu0, umu0, uq0 * 0.015625f) + 1e-5f);
    float urs1 = rsqrtf(fmaf(-umu1, umu1, uq1 * 0.015625f) + 1e-5f);
#pragma unroll
    for (int nn = 0; nn < 8; nn++) {
        float2 g2 = *(const float2*)(pG + nn * 8 + 2 * q);
        float2 h2 = *(const float2*)(pH + nn * 8 + 2 * q);
        v[nn][0] = fmaxf(fmaf((v[nn][0] - vmu0) * vrs0, g2.x, h2.x), 0.f);
        v[nn][1] = fmaxf(fmaf((v[nn][1] - vmu0) * vrs0, g2.y, h2.y), 0.f);
        v[nn][2] = fmaxf(fmaf((v[nn][2] - vmu1) * vrs1, g2.x, h2.x), 0.f);
        v[nn][3] = fmaxf(fmaf((v[nn][3] - vmu1) * vrs1, g2.y, h2.y), 0.f);
        u[nn][0] = fmaxf(fmaf((u[nn][0] - umu0) * urs0, g2.x, h2.x), 0.f);
        u[nn][1] = fmaxf(fmaf((u[nn][1] - umu0) * urs0, g2.y, h2.y), 0.f);
        u[nn][2] = fmaxf(fmaf((u[nn][2] - umu1) * urs1, g2.x, h2.x), 0.f);
        u[nn][3] = fmaxf(fmaf((u[nn][3] - umu1) * urs1, g2.y, h2.y), 0.f);
    }
}

// 444 blocks = one exact wave at 3 blocks/SM on 148 SMs.
// block b: model m = b % 64, chunk j = b / 64. Models 0..59 have 7 blocks, 60..63 have 6.
__global__ void __launch_bounds__(128, 3) mlp_kernel(
    const float* __restrict__ x,
    const float* __restrict__ W0, const float* __restrict__ B0,
    const float* __restrict__ G0, const float* __restrict__ H0,
    const float* __restrict__ W1, const float* __restrict__ B1,
    const float* __restrict__ G1, const float* __restrict__ H1,
    const float* __restrict__ W2, const float* __restrict__ B2,
    const float* __restrict__ G2, const float* __restrict__ H2,
    const float* __restrict__ W3, const float* __restrict__ B3,
    const float* __restrict__ G3, const float* __restrict__ H3,
    const float* __restrict__ W4, const float* __restrict__ B4,
    float* __restrict__ out)
{
    extern __shared__ float sm[];
    const int tid = threadIdx.x;
    const int w = tid >> 5;
    const int lane = tid & 31;
    const int g = lane >> 2;
    const int q = lane & 3;
    const int b = blockIdx.x;
    const int m = b & 63;
    const int j = b >> 6;
    const int nb = (m < 60) ? 7 : 6;
    const int base = g_offsets[m];
    const int cnt = g_offsets[m + 1] - base;
    if (j * 128 >= cnt) return;

    // ---- build fp16 fragment-ordered weights in SMEM ----
    {
        // layers 1..3: k16 frags. entry (kk,nn,lane(g',q')):
        //   n = nn*8+g', b0 = {W[n][16kk+2q'], W[n][16kk+2q'+1]}, b1 = same +8.
        const float* Ws[3] = { W1 + m * 4096, W2 + m * 4096, W3 + m * 4096 };
        uint2* bf = (uint2*)(sm + OFF_BF);
        for (int l = 0; l < 3; l++) {
            const float* Wl = Ws[l];
            for (int jj = tid; jj < 1024; jj += 128) {
                int ln = jj & 31, nk = jj >> 5;      // nk in [0,32): kk*8+nn
                int kk = nk >> 3, nn = nk & 7;
                int n = nn * 8 + (ln >> 2);
                int kb = kk * 16 + 2 * (ln & 3);
                float2 wlo = *(const float2*)(Wl + n * 64 + kb);
                float2 whi = *(const float2*)(Wl + n * 64 + kb + 8);
                bf[l * 1024 + jj] = make_uint2(packh2(wlo.x, wlo.y), packh2(whi.x, whi.y));
            }
        }
        // layer0 k8 frags (K padded to 8; k==6 carries bias via constant-1 input)
        uint32_t* b0f = (uint32_t*)(sm + OFF_B0F);
        for (int jj = tid; jj < 256; jj += 128) {
            int ln = jj & 31, nn = jj >> 5;
            int n = nn * 8 + (ln >> 2);
            int k0 = 2 * (ln & 3);                 // 0,2,4,6
            float v0 = (k0 < 6) ? W0[m * 384 + n * 6 + k0] : B0[m * 64 + n];
            float v1 = (k0 + 1 < 6) ? W0[m * 384 + n * 6 + k0 + 1] : 0.0f;
            b0f[jj] = packh2(v0, v1);
        }
        if (tid < 64) {
            sm[OFF_GH0 + tid]       = G0[m * 64 + tid];
            sm[OFF_GH0 + 64 + tid]  = H0[m * 64 + tid];
            sm[OFF_BGH + tid]       = B1[m * 64 + tid];
            sm[OFF_BGH + 64 + tid]  = G1[m * 64 + tid];
            sm[OFF_BGH + 128 + tid] = H1[m * 64 + tid];
            sm[OFF_BGH + 192 + tid] = B2[m * 64 + tid];
            sm[OFF_BGH + 256 + tid] = G2[m * 64 + tid];
            sm[OFF_BGH + 320 + tid] = H2[m * 64 + tid];
            sm[OFF_BGH + 384 + tid] = B3[m * 64 + tid];
            sm[OFF_BGH + 448 + tid] = G3[m * 64 + tid];
            sm[OFF_BGH + 512 + tid] = H3[m * 64 + tid];
        }
        for (int i = tid; i < 192; i += 128) sm[OFF_W4 + i] = W4[m * 192 + i];
        if (tid < 3) sm[OFF_B4 + tid] = B4[m * 3 + tid];
    }
    __syncthreads();

    uint32_t* stg = (uint32_t*)(sm + OFF_STAGE);
    const uint32_t* b0f = (const uint32_t*)(sm + OFF_B0F);
    const uint2* bf  = (const uint2*)(sm + OFF_BF);
    const int rbase = w * 32;

    for (int t0 = j * 128; t0 < cnt; t0 += nb * 128) {
        const int pos = t0 + tid;
        const int posc = min(pos, cnt - 1);
        const int smp = g_perm[base + posc];

        // stage this thread's sample row as 4 f16x2 words (6 feats + 1.0 + 0)
        {
            float2 x0 = *(const float2*)(x + smp * 6);
            float2 x1 = *(const float2*)(x + smp * 6 + 2);
            float2 x2 = *(const float2*)(x + smp * 6 + 4);
            stg[tid * 4 + 0] = packh2(x0.x, x0.y);
            stg[tid * 4 + 1] = packh2(x1.x, x1.y);
            stg[tid * 4 + 2] = packh2(x2.x, x2.y);
            stg[tid * 4 + 3] = 0x00003C00u;   // {lo=1.0h (bias), hi=0}
        }
        __syncwarp();

        // ---- layer 0: both m-tiles, k8 f16, each B frag loaded once ----
        float h0[8][4], h1[8][4];
        {
            uint32_t a00 = stg[(rbase + g) * 4 + q];
            uint32_t a01 = stg[(rbase + g + 8) * 4 + q];
            uint32_t a10 = stg[(rbase + 16 + g) * 4 + q];
            uint32_t a11 = stg[(rbase + 24 + g) * 4 + q];
#pragma unroll
            for (int nn = 0; nn < 8; nn++) {
                h0[nn][0] = h0[nn][1] = h0[nn][2] = h0[nn][3] = 0.f;
                h1[nn][0] = h1[nn][1] = h1[nn][2] = h1[nn][3] = 0.f;
                uint32_t bb = b0f[nn * 32 + lane];
                mma_f16_k8(h0[nn], a00, a01, bb);
                mma_f16_k8(h1[nn], a10, a11, bb);
            }
        }
        ln16x2(h0, h1, nullptr, sm + OFF_GH0, sm + OFF_GH0 + 64, q);

        // ---- layers 1..3: k16 f16; D feeds A naturally (2 n-tiles = 1 k-group) ----
#pragma unroll 1
        for (int l = 0; l < 3; l++) {
            float d0[8][4], d1[8][4];
#pragma unroll
            for (int nn = 0; nn < 8; nn++) {
                d0[nn][0] = d0[nn][1] = d0[nn][2] = d0[nn][3] = 0.f;
                d1[nn][0] = d1[nn][1] = d1[nn][2] = d1[nn][3] = 0.f;
            }
            const uint2* bl = bf + l * 1024 + lane;
#pragma unroll
            for (int kk = 0; kk < 4; kk++) {
                uint32_t a00 = packh2(h0[2 * kk][0],     h0[2 * kk][1]);
                uint32_t a01 = packh2(h0[2 * kk][2],     h0[2 * kk][3]);
                uint32_t a02 = packh2(h0[2 * kk + 1][0], h0[2 * kk + 1][1]);
                uint32_t a03 = packh2(h0[2 * kk + 1][2], h0[2 * kk + 1][3]);
                uint32_t a10 = packh2(h1[2 * kk][0],     h1[2 * kk][1]);
                uint32_t a11 = packh2(h1[2 * kk][2],     h1[2 * kk][3]);
                uint32_t a12 = packh2(h1[2 * kk + 1][0], h1[2 * kk + 1][1]);
                uint32_t a13 = packh2(h1[2 * kk + 1][2], h1[2 * kk + 1][3]);
#pragma unroll
                for (int nn = 0; nn < 8; nn++) {
                    uint2 bb = bl[(kk * 8 + nn) * 32];
                    mma_f16_k16(d0[nn], a00, a01, a02, a03, bb.x, bb.y);
                    mma_f16_k16(d1[nn], a10, a11, a12, a13, bb.x, bb.y);
                }
            }
            const float* pB = sm + OFF_BGH + l * 192;
            ln16x2(d0, d1, pB, pB + 64, pB + 128, q);
#pragma unroll
            for (int nn = 0; nn < 8; nn++) {
                h0[nn][0] = d0[nn][0]; h0[nn][1] = d0[nn][1];
                h0[nn][2] = d0[nn][2]; h0[nn][3] = d0[nn][3];
                h1[nn][0] = d1[nn][0]; h1[nn][1] = d1[nn][1];
                h1[nn][2] = d1[nn][2]; h1[nn][3] = d1[nn][3];
            }
        }

        // ---- head: 64 -> 3, both tiles, W4 loaded once (fp32) ----
        float p000 = 0.f, p001 = 0.f, p002 = 0.f, p010 = 0.f, p011 = 0.f, p012 = 0.f;
        float p100 = 0.f, p101 = 0.f, p102 = 0.f, p110 = 0.f, p111 = 0.f, p112 = 0.f;
#pragma unroll
        for (int nn = 0; nn < 8; nn++) {
            float2 w0 = *(const float2*)(sm + OFF_W4 + 0 * 64 + nn * 8 + 2 * q);
            float2 w1 = *(const float2*)(sm + OFF_W4 + 1 * 64 + nn * 8 + 2 * q);
            float2 w2 = *(const float2*)(sm + OFF_W4 + 2 * 64 + nn * 8 + 2 * q);
            p000 = fmaf(w0.x, h0[nn][0], fmaf(w0.y, h0[nn][1], p000));
            p010 = fmaf(w0.x, h0[nn][2], fmaf(w0.y, h0[nn][3], p010));
            p001 = fmaf(w1.x, h0[nn][0], fmaf(w1.y, h0[nn][1], p001));
            p011 = fmaf(w1.x, h0[nn][2], fmaf(w1.y, h0[nn][3], p011));
            p002 = fmaf(w2.x, h0[nn][0], fmaf(w2.y, h0[nn][1], p002));
            p012 = fmaf(w2.x, h0[nn][2], fmaf(w2.y, h0[nn][3], p012));
            p100 = fmaf(w0.x, h1[nn][0], fmaf(w0.y, h1[nn][1], p100));
            p110 = fmaf(w0.x, h1[nn][2], fmaf(w0.y, h1[nn][3], p110));
            p101 = fmaf(w1.x, h1[nn][0], fmaf(w1.y, h1[nn][1], p101));
            p111 = fmaf(w1.x, h1[nn][2], fmaf(w1.y, h1[nn][3], p111));
            p102 = fmaf(w2.x, h1[nn][0], fmaf(w2.y, h1[nn][1], p102));
            p112 = fmaf(w2.x, h1[nn][2], fmaf(w2.y, h1[nn][3], p112));
        }
#pragma unroll
        for (int msk = 1; msk <= 2; msk <<= 1) {
            p000 += __shfl_xor_sync(0xffffffffu, p000, msk);
            p001 += __shfl_xor_sync(0xffffffffu, p001, msk);
            p002 += __shfl_xor_sync(0xffffffffu, p002, msk);
            p010 += __shfl_xor_sync(0xffffffffu, p010, msk);
            p011 += __shfl_xor_sync(0xffffffffu, p011, msk);
            p012 += __shfl_xor_sync(0xffffffffu, p012, msk);
            p100 += __shfl_xor_sync(0xffffffffu, p100, msk);
            p101 += __shfl_xor_sync(0xffffffffu, p101, msk);
            p102 += __shfl_xor_sync(0xffffffffu, p102, msk);
            p110 += __shfl_xor_sync(0xffffffffu, p110, msk);
            p111 += __shfl_xor_sync(0xffffffffu, p111, msk);
            p112 += __shfl_xor_sync(0xffffffffu, p112, msk);
        }
        int s_r0 = __shfl_sync(0xffffffffu, smp, g);
        int s_r1 = __shfl_sync(0xffffffffu, smp, g + 8);
        int s_r2 = __shfl_sync(0xffffffffu, smp, 16 + g);
        int s_r3 = __shfl_sync(0xffffffffu, smp, 24 + g);
        int pr = t0 + rbase + g;
        if (q < 3) {
            float v0 = (q == 0) ? p000 : (q == 1) ? p001 : p002;
            float v1 = (q == 0) ? p010 : (q == 1) ? p011 : p012;
            float v2 = (q == 0) ? p100 : (q == 1) ? p101 : p102;
            float v3 = (q == 0) ? p110 : (q == 1) ? p111 : p112;
            float bq = sm[OFF_B4 + q];
            if (pr < cnt)      out[s_r0 * 3 + q] = v0 + bq;
            if (pr + 8 < cnt)  out[s_r1 * 3 + q] = v1 + bq;
            if (pr + 16 < cnt) out[s_r2 * 3 + q] = v2 + bq;
            if (pr + 24 < cnt) out[s_r3 * 3 + q] = v3 + bq;
        }
    }
}

// ---------------- launch -----------------------------------------------------
extern "C" void kernel_launch(void* const* d_in, const int* in_sizes, int n_in,
                              void* d_out, int out_size) {
    const float* x  = (const float*)d_in[0];
    const int* idx  = (const int*)d_in[1];
    const float* W0 = (const float*)d_in[2];
    const float* B0 = (const float*)d_in[3];
    const float* G0 = (const float*)d_in[4];
    const float* H0 = (const float*)d_in[5];
    const float* W1 = (const float*)d_in[6];
    const float* B1 = (const float*)d_in[7];
    const float* G1 = (const float*)d_in[8];
    const float* H1 = (const float*)d_in[9];
    const float* W2 = (const float*)d_in[10];
    const float* B2 = (const float*)d_in[11];
    const float* G2 = (const float*)d_in[12];
    const float* H2 = (const float*)d_in[13];
    const float* W3 = (const float*)d_in[14];
    const float* B3 = (const float*)d_in[15];
    const float* G3 = (const float*)d_in[16];
    const float* H3 = (const float*)d_in[17];
    const float* W4 = (const float*)d_in[18];
    const float* B4 = (const float*)d_in[19];
    float* out = (float*)d_out;

    int N = in_sizes[1];
    if (N > MAXN) N = MAXN;

    cudaFuncSetAttribute(mlp_kernel, cudaFuncAttributeMaxDynamicSharedMemorySize,
                         SMEM_FLOATS * (int)sizeof(float));

    hist_kernel<<<512, 256>>>(idx, N);
    scan_kernel<<<1, 64>>>();
    scatter_kernel<<<512, 256>>>(idx, N);

    mlp_kernel<<<444, 128, SMEM_FLOATS * (int)sizeof(float)>>>(
        x, W0, B0, G0, H0, W1, B1, G1, H1, W2, B2, G2, H2, W3, B3, G3, H3, W4, B4, out);
}

// round 11
// speedup vs baseline: 5.6379x; 1.0394x over previous
#include <cuda_runtime.h>
#include <cstdint>

#define NM 64
#define MAXN 262144

// ---------------- scratch ---------------------------------------------------
__device__ int g_counts[NM];        // statically zero-init; re-zeroed by scan_kernel
__device__ int g_offsets[NM + 1];
__device__ int g_cursor[NM];
__device__ int g_perm[MAXN];

// ---------------- prep kernels ----------------------------------------------
__global__ void hist_kernel(const int* __restrict__ idx, int N) {
    __shared__ int lc[NM];
    if (threadIdx.x < NM) lc[threadIdx.x] = 0;
    __syncthreads();
    for (int i = blockIdx.x * blockDim.x + threadIdx.x; i < N; i += gridDim.x * blockDim.x)
        atomicAdd(&lc[idx[i]], 1);
    __syncthreads();
    if (threadIdx.x < NM) atomicAdd(&g_counts[threadIdx.x], lc[threadIdx.x]);
}

__global__ void scan_kernel() {
    __shared__ int s[NM];
    int t = threadIdx.x;
    s[t] = g_counts[t];
    __syncthreads();
    if (t == 0) {
        int acc = 0;
        for (int i = 0; i < NM; i++) { int c = s[i]; s[i] = acc; acc += c; }
        g_offsets[NM] = acc;
    }
    __syncthreads();
    g_offsets[t] = s[t];
    g_cursor[t]  = s[t];
    g_counts[t]  = 0;     // pre-zero for the next kernel_launch invocation
}

__global__ void scatter_kernel(const int* __restrict__ idx, int N) {
    __shared__ int lc[NM];
    __shared__ int lbase[NM];
    int t = threadIdx.x;
    int per = (N + gridDim.x - 1) / gridDim.x;
    int lo = blockIdx.x * per;
    int hi = min(lo + per, N);
    if (t < NM) lc[t] = 0;
    __syncthreads();
    for (int i = lo + t; i < hi; i += blockDim.x)
        atomicAdd(&lc[idx[i]], 1);
    __syncthreads();
    if (t < NM) { lbase[t] = atomicAdd(&g_cursor[t], lc[t]); lc[t] = 0; }
    __syncthreads();
    for (int i = lo + t; i < hi; i += blockDim.x) {
        int m = idx[i];
        int r = atomicAdd(&lc[m], 1);
        g_perm[lbase[m] + r] = i;
    }
}

// ---------------- mma helpers ------------------------------------------------
__device__ __forceinline__ uint32_t packh2(float lo, float hi) {
    uint32_t u;
    asm("cvt.rn.f16x2.f32 %0, %1, %2;" : "=r"(u) : "f"(hi), "f"(lo));
    return u;
}

__device__ __forceinline__ void mma_f16_k8(float* d, uint32_t a0, uint32_t a1, uint32_t b0) {
    asm volatile(
        "mma.sync.aligned.m16n8k8.row.col.f32.f16.f16.f32 "
        "{%0,%1,%2,%3}, {%4,%5}, {%6}, {%0,%1,%2,%3};"
        : "+f"(d[0]), "+f"(d[1]), "+f"(d[2]), "+f"(d[3])
        : "r"(a0), "r"(a1), "r"(b0));
}

__device__ __forceinline__ void mma_f16_k16(float* d, uint32_t a0, uint32_t a1,
                                            uint32_t a2, uint32_t a3,
                                            uint32_t b0, uint32_t b1) {
    asm volatile(
        "mma.sync.aligned.m16n8k16.row.col.f32.f16.f16.f32 "
        "{%0,%1,%2,%3}, {%4,%5,%6,%7}, {%8,%9}, {%0,%1,%2,%3};"
        : "+f"(d[0]), "+f"(d[1]), "+f"(d[2]), "+f"(d[3])
        : "r"(a0), "r"(a1), "r"(a2), "r"(a3), "r"(b0), "r"(b1));
}

// ---------------- SMEM layout (floats) ---------------------------------------
// BF per layer = 4kk * 8nn * 32 lanes * uint2 = 1024 uint2 = 2048 floats.
#define OFF_STAGE 0        // 128 rows x 4 uints (x as f16x2, K padded to 8)
#define OFF_B0F   512      // layer0 B frags: 8nn x 32 lanes x uint = 256
#define OFF_BF    768      // layers 1..3 B frags: 3 x 2048 fl = 6144
#define OFF_GH0   6912     // G0|H0 (128)
#define OFF_BGH   7040     // layers 1..3: B|G|H (192 each) = 576
#define OFF_HF    7616     // head frags: 4kk x 32 lanes x uint2 = 256
#define OFF_B4    7872     // 4
#define SMEM_FLOATS 7876

// Fused LayerNorm + ReLU on TWO warp m-tiles held as D fragments.
// Output: packed f16x2 A-registers for the next mma (and the head).
// ap0[nn] = {v[nn][0], v[nn][1]} (row g), ap1[nn] = {v[nn][2], v[nn][3]} (row g+8).
__device__ __forceinline__ void ln16x2_pack(float v[8][4], float u[8][4], const float* pB,
                                            const float* pG, const float* pH, int q,
                                            uint32_t* ap0, uint32_t* ap1,
                                            uint32_t* bp0, uint32_t* bp1) {
    if (pB) {
#pragma unroll
        for (int nn = 0; nn < 8; nn++) {
            float2 bb = *(const float2*)(pB + nn * 8 + 2 * q);
            v[nn][0] += bb.x; v[nn][1] += bb.y; v[nn][2] += bb.x; v[nn][3] += bb.y;
            u[nn][0] += bb.x; u[nn][1] += bb.y; u[nn][2] += bb.x; u[nn][3] += bb.y;
        }
    }
    float vs0 = 0.f, vs1 = 0.f, vq0 = 0.f, vq1 = 0.f;
    float us0 = 0.f, us1 = 0.f, uq0 = 0.f, uq1 = 0.f;
#pragma unroll
    for (int nn = 0; nn < 8; nn++) {
        vs0 += v[nn][0]; vq0 = fmaf(v[nn][0], v[nn][0], vq0);
        vs0 += v[nn][1]; vq0 = fmaf(v[nn][1], v[nn][1], vq0);
        vs1 += v[nn][2]; vq1 = fmaf(v[nn][2], v[nn][2], vq1);
        vs1 += v[nn][3]; vq1 = fmaf(v[nn][3], v[nn][3], vq1);
        us0 += u[nn][0]; uq0 = fmaf(u[nn][0], u[nn][0], uq0);
        us0 += u[nn][1]; uq0 = fmaf(u[nn][1], u[nn][1], uq0);
        us1 += u[nn][2]; uq1 = fmaf(u[nn][2], u[nn][2], uq1);
        us1 += u[nn][3]; uq1 = fmaf(u[nn][3], u[nn][3], uq1);
    }
#pragma unroll
    for (int msk = 1; msk <= 2; msk <<= 1) {
        vs0 += __shfl_xor_sync(0xffffffffu, vs0, msk);
        vq0 += __shfl_xor_sync(0xffffffffu, vq0, msk);
        vs1 += __shfl_xor_sync(0xffffffffu, vs1, msk);
        vq1 += __shfl_xor_sync(0xffffffffu, vq1, msk);
        us0 += __shfl_xor_sync(0xffffffffu, us0, msk);
        uq0 += __shfl_xor_sync(0xffffffffu, uq0, msk);
        us1 += __shfl_xor_sync(0xffffffffu, us1, msk);
        uq1 += __shfl_xor_sync(0xffffffffu, uq1, msk);
    }
    float vmu0 = vs0 * 0.015625f, vmu1 = vs1 * 0.015625f;
    float umu0 = us0 * 0.015625f, umu1 = us1 * 0.015625f;
    float vrs0 = rsqrtf(fmaf(-vmu0, vmu0, vq0 * 0.015625f) + 1e-5f);
    float vrs1 = rsqrtf(fmaf(-vmu1, vmu1, vq1 * 0.015625f) + 1e-5f);
    float urs0 = rsqrtf(fmaf(-umu0, umu0, uq0 * 0.015625f) + 1e-5f);
    float urs1 = rsqrtf(fmaf(-umu1, umu1, uq1 * 0.015625f) + 1e-5f);
#pragma unroll
    for (int nn = 0; nn < 8; nn++) {
        float2 g2 = *(const float2*)(pG + nn * 8 + 2 * q);
        float2 h2 = *(const float2*)(pH + nn * 8 + 2 * q);
        float a0 = fmaxf(fmaf((v[nn][0] - vmu0) * vrs0, g2.x, h2.x), 0.f);
        float a1 = fmaxf(fmaf((v[nn][1] - vmu0) * vrs0, g2.y, h2.y), 0.f);
        float a2 = fmaxf(fmaf((v[nn][2] - vmu1) * vrs1, g2.x, h2.x), 0.f);
        float a3 = fmaxf(fmaf((v[nn][3] - vmu1) * vrs1, g2.y, h2.y), 0.f);
        ap0[nn] = packh2(a0, a1);
        ap1[nn] = packh2(a2, a3);
        float b0 = fmaxf(fmaf((u[nn][0] - umu0) * urs0, g2.x, h2.x), 0.f);
        float b1 = fmaxf(fmaf((u[nn][1] - umu0) * urs0, g2.y, h2.y), 0.f);
        float b2 = fmaxf(fmaf((u[nn][2] - umu1) * urs1, g2.x, h2.x), 0.f);
        float b3 = fmaxf(fmaf((u[nn][3] - umu1) * urs1, g2.y, h2.y), 0.f);
        bp0[nn] = packh2(b0, b1);
        bp1[nn] = packh2(b2, b3);
    }
}

// 592 blocks = one exact wave at 4 blocks/SM on 148 SMs.
// block b: model m = b % 64, chunk j = b / 64. Models 0..15 have 10 blocks, 16..63 have 9.
__global__ void __launch_bounds__(128, 4) mlp_kernel(
    const float* __restrict__ x,
    const float* __restrict__ W0, const float* __restrict__ B0,
    const float* __restrict__ G0, const float* __restrict__ H0,
    const float* __restrict__ W1, const float* __restrict__ B1,
    const float* __restrict__ G1, const float* __restrict__ H1,
    const float* __restrict__ W2, const float* __restrict__ B2,
    const float* __restrict__ G2, const float* __restrict__ H2,
    const float* __restrict__ W3, const float* __restrict__ B3,
    const float* __restrict__ G3, const float* __restrict__ H3,
    const float* __restrict__ W4, const float* __restrict__ B4,
    float* __restrict__ out)
{
    extern __shared__ float sm[];
    const int tid = threadIdx.x;
    const int w = tid >> 5;
    const int lane = tid & 31;
    const int g = lane >> 2;
    const int q = lane & 3;
    const int b = blockIdx.x;
    const int m = b & 63;
    const int j = b >> 6;
    const int nb = (m < 16) ? 10 : 9;
    const int base = g_offsets[m];
    const int cnt = g_offsets[m + 1] - base;
    if (j * 128 >= cnt) return;

    // ---- build fp16 fragment-ordered weights in SMEM ----
    {
        // layers 1..3: k16 frags. entry (kk,nn,lane(g',q')):
        //   n = nn*8+g', b0 = {W[n][16kk+2q'], W[n][16kk+2q'+1]}, b1 = same +8.
        const float* Ws[3] = { W1 + m * 4096, W2 + m * 4096, W3 + m * 4096 };
        uint2* bf = (uint2*)(sm + OFF_BF);
        for (int l = 0; l < 3; l++) {
            const float* Wl = Ws[l];
            for (int jj = tid; jj < 1024; jj += 128) {
                int ln = jj & 31, nk = jj >> 5;
                int kk = nk >> 3, nn = nk & 7;
                int n = nn * 8 + (ln >> 2);
                int kb = kk * 16 + 2 * (ln & 3);
                float2 wlo = *(const float2*)(Wl + n * 64 + kb);
                float2 whi = *(const float2*)(Wl + n * 64 + kb + 8);
                bf[l * 1024 + jj] = make_uint2(packh2(wlo.x, wlo.y), packh2(whi.x, whi.y));
            }
        }
        // layer0 k8 frags (K padded to 8; k==6 carries bias via constant-1 input)
        uint32_t* b0f = (uint32_t*)(sm + OFF_B0F);
        for (int jj = tid; jj < 256; jj += 128) {
            int ln = jj & 31, nn = jj >> 5;
            int n = nn * 8 + (ln >> 2);
            int k0 = 2 * (ln & 3);                 // 0,2,4,6
            float v0 = (k0 < 6) ? W0[m * 384 + n * 6 + k0] : B0[m * 64 + n];
            float v1 = (k0 + 1 < 6) ? W0[m * 384 + n * 6 + k0 + 1] : 0.0f;
            b0f[jj] = packh2(v0, v1);
        }
        // head k16 frags: n = ln>>2 (rows 3..7 zero), same k layout as layers
        uint2* hf = (uint2*)(sm + OFF_HF);
        {
            int ln = tid & 31, kk = tid >> 5;
            if (kk < 4) {
                int n = ln >> 2;
                uint2 v = make_uint2(0u, 0u);
                if (n < 3) {
                    int kb = kk * 16 + 2 * (ln & 3);
                    const float* Wh = W4 + m * 192 + n * 64;
                    float2 wlo = *(const float2*)(Wh + kb);
                    float2 whi = *(const float2*)(Wh + kb + 8);
                    v = make_uint2(packh2(wlo.x, wlo.y), packh2(whi.x, whi.y));
                }
                hf[tid] = v;
            }
        }
        if (tid < 64) {
            sm[OFF_GH0 + tid]       = G0[m * 64 + tid];
            sm[OFF_GH0 + 64 + tid]  = H0[m * 64 + tid];
            sm[OFF_BGH + tid]       = B1[m * 64 + tid];
            sm[OFF_BGH + 64 + tid]  = G1[m * 64 + tid];
            sm[OFF_BGH + 128 + tid] = H1[m * 64 + tid];
            sm[OFF_BGH + 192 + tid] = B2[m * 64 + tid];
            sm[OFF_BGH + 256 + tid] = G2[m * 64 + tid];
            sm[OFF_BGH + 320 + tid] = H2[m * 64 + tid];
            sm[OFF_BGH + 384 + tid] = B3[m * 64 + tid];
            sm[OFF_BGH + 448 + tid] = G3[m * 64 + tid];
            sm[OFF_BGH + 512 + tid] = H3[m * 64 + tid];
        }
        if (tid < 3) sm[OFF_B4 + tid] = B4[m * 3 + tid];
    }
    __syncthreads();

    uint32_t* stg = (uint32_t*)(sm + OFF_STAGE);
    const uint32_t* b0f = (const uint32_t*)(sm + OFF_B0F);
    const uint2* bf  = (const uint2*)(sm + OFF_BF);
    const uint2* hf  = (const uint2*)(sm + OFF_HF) + lane;
    const int rbase = w * 32;
    const float b4_0 = sm[OFF_B4 + 0];
    const float b4_1 = sm[OFF_B4 + 1];
    const float b4_2 = sm[OFF_B4 + 2];

    for (int t0 = j * 128; t0 < cnt; t0 += nb * 128) {
        const int pos = t0 + tid;
        const int posc = min(pos, cnt - 1);
        const int smp = g_perm[base + posc];

        // stage this thread's sample row as 4 f16x2 words (6 feats + 1.0 + 0)
        {
            float2 x0 = *(const float2*)(x + smp * 6);
            float2 x1 = *(const float2*)(x + smp * 6 + 2);
            float2 x2 = *(const float2*)(x + smp * 6 + 4);
            stg[tid * 4 + 0] = packh2(x0.x, x0.y);
            stg[tid * 4 + 1] = packh2(x1.x, x1.y);
            stg[tid * 4 + 2] = packh2(x2.x, x2.y);
            stg[tid * 4 + 3] = 0x00003C00u;   // {lo=1.0h (bias), hi=0}
        }
        __syncwarp();

        float d0[8][4], d1[8][4];
        uint32_t ap0[8], ap1[8], bp0[8], bp1[8];

        // ---- layer 0: both m-tiles, k8 f16, each B frag loaded once ----
        {
            uint32_t a00 = stg[(rbase + g) * 4 + q];
            uint32_t a01 = stg[(rbase + g + 8) * 4 + q];
            uint32_t a10 = stg[(rbase + 16 + g) * 4 + q];
            uint32_t a11 = stg[(rbase + 24 + g) * 4 + q];
#pragma unroll
            for (int nn = 0; nn < 8; nn++) {
                d0[nn][0] = d0[nn][1] = d0[nn][2] = d0[nn][3] = 0.f;
                d1[nn][0] = d1[nn][1] = d1[nn][2] = d1[nn][3] = 0.f;
                uint32_t bb = b0f[nn * 32 + lane];
                mma_f16_k8(d0[nn], a00, a01, bb);
                mma_f16_k8(d1[nn], a10, a11, bb);
            }
        }
        ln16x2_pack(d0, d1, nullptr, sm + OFF_GH0, sm + OFF_GH0 + 64, q,
                    ap0, ap1, bp0, bp1);

        // ---- layers 1..3: k16 f16; packed A regs feed mma directly ----
#pragma unroll 1
        for (int l = 0; l < 3; l++) {
#pragma unroll
            for (int nn = 0; nn < 8; nn++) {
                d0[nn][0] = d0[nn][1] = d0[nn][2] = d0[nn][3] = 0.f;
                d1[nn][0] = d1[nn][1] = d1[nn][2] = d1[nn][3] = 0.f;
            }
            const uint2* bl = bf + l * 1024 + lane;
#pragma unroll
            for (int kk = 0; kk < 4; kk++) {
#pragma unroll
                for (int nn = 0; nn < 8; nn++) {
                    uint2 bb = bl[(kk * 8 + nn) * 32];
                    mma_f16_k16(d0[nn], ap0[2 * kk], ap1[2 * kk],
                                ap0[2 * kk + 1], ap1[2 * kk + 1], bb.x, bb.y);
                    mma_f16_k16(d1[nn], bp0[2 * kk], bp1[2 * kk],
                                bp0[2 * kk + 1], bp1[2 * kk + 1], bb.x, bb.y);
                }
            }
            const float* pB = sm + OFF_BGH + l * 192;
            ln16x2_pack(d0, d1, pB, pB + 64, pB + 128, q, ap0, ap1, bp0, bp1);
        }

        // ---- head: 64 -> 3 via mma (N padded to 8) ----
        float e0[4] = {0.f, 0.f, 0.f, 0.f};
        float e1[4] = {0.f, 0.f, 0.f, 0.f};
#pragma unroll
        for (int kk = 0; kk < 4; kk++) {
            uint2 bb = hf[kk * 32];
            mma_f16_k16(e0, ap0[2 * kk], ap1[2 * kk], ap0[2 * kk + 1], ap1[2 * kk + 1],
                        bb.x, bb.y);
            mma_f16_k16(e1, bp0[2 * kk], bp1[2 * kk], bp0[2 * kk + 1], bp1[2 * kk + 1],
                        bb.x, bb.y);
        }
        // D frag: lane(g,q) holds (row g, col 2q), (row g, col 2q+1),
        //         (row g+8, col 2q), (row g+8, col 2q+1). Valid cols: 0,1,2.
        int s_r0 = __shfl_sync(0xffffffffu, smp, g);
        int s_r1 = __shfl_sync(0xffffffffu, smp, g + 8);
        int s_r2 = __shfl_sync(0xffffffffu, smp, 16 + g);
        int s_r3 = __shfl_sync(0xffffffffu, smp, 24 + g);
        int pr = t0 + rbase + g;
        if (q == 0) {
            if (pr < cnt)      { out[s_r0 * 3 + 0] = e0[0] + b4_0; out[s_r0 * 3 + 1] = e0[1] + b4_1; }
            if (pr + 8 < cnt)  { out[s_r1 * 3 + 0] = e0[2] + b4_0; out[s_r1 * 3 + 1] = e0[3] + b4_1; }
            if (pr + 16 < cnt) { out[s_r2 * 3 + 0] = e1[0] + b4_0; out[s_r2 * 3 + 1] = e1[1] + b4_1; }
            if (pr + 24 < cnt) { out[s_r3 * 3 + 0] = e1[2] + b4_0; out[s_r3 * 3 + 1] = e1[3] + b4_1; }
        } else if (q == 1) {
            if (pr < cnt)      out[s_r0 * 3 + 2] = e0[0] + b4_2;
            if (pr + 8 < cnt)  out[s_r1 * 3 + 2] = e0[2] + b4_2;
            if (pr + 16 < cnt) out[s_r2 * 3 + 2] = e1[0] + b4_2;
            if (pr + 24 < cnt) out[s_r3 * 3 + 2] = e1[2] + b4_2;
        }
    }
}

// ---------------- launch -----------------------------------------------------
extern "C" void kernel_launch(void* const* d_in, const int* in_sizes, int n_in,
                              void* d_out, int out_size) {
    const float* x  = (const float*)d_in[0];
    const int* idx  = (const int*)d_in[1];
    const float* W0 = (const float*)d_in[2];
    const float* B0 = (const float*)d_in[3];
    const float* G0 = (const float*)d_in[4];
    const float* H0 = (const float*)d_in[5];
    const float* W1 = (const float*)d_in[6];
    const float* B1 = (const float*)d_in[7];
    const float* G1 = (const float*)d_in[8];
    const float* H1 = (const float*)d_in[9];
    const float* W2 = (const float*)d_in[10];
    const float* B2 = (const float*)d_in[11];
    const float* G2 = (const float*)d_in[12];
    const float* H2 = (const float*)d_in[13];
    const float* W3 = (const float*)d_in[14];
    const float* B3 = (const float*)d_in[15];
    const float* G3 = (const float*)d_in[16];
    const float* H3 = (const float*)d_in[17];
    const float* W4 = (const float*)d_in[18];
    const float* B4 = (const float*)d_in[19];
    float* out = (float*)d_out;

    int N = in_sizes[1];
    if (N > MAXN) N = MAXN;

    cudaFuncSetAttribute(mlp_kernel, cudaFuncAttributeMaxDynamicSharedMemorySize,
                         SMEM_FLOATS * (int)sizeof(float));

    hist_kernel<<<512, 256>>>(idx, N);
    scan_kernel<<<1, 64>>>();
    scatter_kernel<<<512, 256>>>(idx, N);

    mlp_kernel<<<592, 128, SMEM_FLOATS * (int)sizeof(float)>>>(
        x, W0, B0, G0, H0, W1, B1, G1, H1, W2, B2, G2, H2, W3, B3, G3, H3, W4, B4, out);
}

// round 12
// speedup vs baseline: 6.1532x; 1.0914x over previous
#include <cuda_runtime.h>
#include <cstdint>

#define NM 64
#define MAXN 262144

// ---------------- scratch ---------------------------------------------------
__device__ int g_counts[NM];        // statically zero-init; re-zeroed by scan_kernel
__device__ int g_offsets[NM + 1];
__device__ int g_cursor[NM];
__device__ int g_perm[MAXN];

// ---------------- prep kernels ----------------------------------------------
__global__ void hist_kernel(const int* __restrict__ idx, int N) {
    __shared__ int lc[NM];
    if (threadIdx.x < NM) lc[threadIdx.x] = 0;
    __syncthreads();
    for (int i = blockIdx.x * blockDim.x + threadIdx.x; i < N; i += gridDim.x * blockDim.x)
        atomicAdd(&lc[idx[i]], 1);
    __syncthreads();
    if (threadIdx.x < NM) atomicAdd(&g_counts[threadIdx.x], lc[threadIdx.x]);
}

__global__ void scan_kernel() {
    __shared__ int s[NM];
    int t = threadIdx.x;
    s[t] = g_counts[t];
    __syncthreads();
    if (t == 0) {
        int acc = 0;
        for (int i = 0; i < NM; i++) { int c = s[i]; s[i] = acc; acc += c; }
        g_offsets[NM] = acc;
    }
    __syncthreads();
    g_offsets[t] = s[t];
    g_cursor[t]  = s[t];
    g_counts[t]  = 0;     // pre-zero for the next kernel_launch invocation
}

__global__ void scatter_kernel(const int* __restrict__ idx, int N) {
    __shared__ int lc[NM];
    __shared__ int lbase[NM];
    int t = threadIdx.x;
    int per = (N + gridDim.x - 1) / gridDim.x;
    int lo = blockIdx.x * per;
    int hi = min(lo + per, N);
    if (t < NM) lc[t] = 0;
    __syncthreads();
    for (int i = lo + t; i < hi; i += blockDim.x)
        atomicAdd(&lc[idx[i]], 1);
    __syncthreads();
    if (t < NM) { lbase[t] = atomicAdd(&g_cursor[t], lc[t]); lc[t] = 0; }
    __syncthreads();
    for (int i = lo + t; i < hi; i += blockDim.x) {
        int m = idx[i];
        int r = atomicAdd(&lc[m], 1);
        g_perm[lbase[m] + r] = i;
    }
}

// ---------------- mma helpers ------------------------------------------------
__device__ __forceinline__ uint32_t packh2(float lo, float hi) {
    uint32_t u;
    asm("cvt.rn.f16x2.f32 %0, %1, %2;" : "=r"(u) : "f"(hi), "f"(lo));
    return u;
}

// relu on a packed f16x2 (sign-exact vs f32 fmax-then-pack)
__device__ __forceinline__ uint32_t hmax2z(uint32_t p) {
    uint32_t r;
    asm("max.f16x2 %0, %1, %2;" : "=r"(r) : "r"(p), "r"(0u));
    return r;
}

__device__ __forceinline__ void mma_f16_k8(float* d, uint32_t a0, uint32_t a1, uint32_t b0) {
    asm volatile(
        "mma.sync.aligned.m16n8k8.row.col.f32.f16.f16.f32 "
        "{%0,%1,%2,%3}, {%4,%5}, {%6}, {%0,%1,%2,%3};"
        : "+f"(d[0]), "+f"(d[1]), "+f"(d[2]), "+f"(d[3])
        : "r"(a0), "r"(a1), "r"(b0));
}

__device__ __forceinline__ void mma_f16_k16(float* d, uint32_t a0, uint32_t a1,
                                            uint32_t a2, uint32_t a3,
                                            uint32_t b0, uint32_t b1) {
    asm volatile(
        "mma.sync.aligned.m16n8k16.row.col.f32.f16.f16.f32 "
        "{%0,%1,%2,%3}, {%4,%5,%6,%7}, {%8,%9}, {%0,%1,%2,%3};"
        : "+f"(d[0]), "+f"(d[1]), "+f"(d[2]), "+f"(d[3])
        : "r"(a0), "r"(a1), "r"(a2), "r"(a3), "r"(b0), "r"(b1));
}

// ---------------- SMEM layout (floats) ---------------------------------------
// BF per layer = 4kk * 8nn * 32 lanes * uint2 = 1024 uint2 = 2048 floats.
#define OFF_STAGE 0        // 128 rows x 4 uints (x as f16x2, K padded to 8)
#define OFF_B0F   512      // layer0 B frags: 8nn x 32 lanes x uint = 256
#define OFF_BF    768      // layers 1..3 B frags: 3 x 2048 fl = 6144
#define OFF_GH0   6912     // G0|H0 (128)
#define OFF_BGH   7040     // layers 1..3: B|G|H (192 each) = 576
#define OFF_HF    7616     // head frags: 4kk x 32 lanes x uint2 = 256
#define OFF_B4    7872     // 4
#define SMEM_FLOATS 7876

// Fused LayerNorm + ReLU on TWO warp m-tiles held as D fragments (bias already
// accumulated inside the mma). Normalize folded to one FMA per element via
// c = -mu*rs; ReLU done on packed f16x2 via max.f16x2.
__device__ __forceinline__ void ln16x2_pack(float v[8][4], float u[8][4],
                                            const float* pG, const float* pH, int q,
                                            uint32_t* ap0, uint32_t* ap1,
                                            uint32_t* bp0, uint32_t* bp1) {
    float vs0 = 0.f, vs1 = 0.f, vq0 = 0.f, vq1 = 0.f;
    float us0 = 0.f, us1 = 0.f, uq0 = 0.f, uq1 = 0.f;
#pragma unroll
    for (int nn = 0; nn < 8; nn++) {
        vs0 += v[nn][0]; vq0 = fmaf(v[nn][0], v[nn][0], vq0);
        vs0 += v[nn][1]; vq0 = fmaf(v[nn][1], v[nn][1], vq0);
        vs1 += v[nn][2]; vq1 = fmaf(v[nn][2], v[nn][2], vq1);
        vs1 += v[nn][3]; vq1 = fmaf(v[nn][3], v[nn][3], vq1);
        us0 += u[nn][0]; uq0 = fmaf(u[nn][0], u[nn][0], uq0);
        us0 += u[nn][1]; uq0 = fmaf(u[nn][1], u[nn][1], uq0);
        us1 += u[nn][2]; uq1 = fmaf(u[nn][2], u[nn][2], uq1);
        us1 += u[nn][3]; uq1 = fmaf(u[nn][3], u[nn][3], uq1);
    }
#pragma unroll
    for (int msk = 1; msk <= 2; msk <<= 1) {
        vs0 += __shfl_xor_sync(0xffffffffu, vs0, msk);
        vq0 += __shfl_xor_sync(0xffffffffu, vq0, msk);
        vs1 += __shfl_xor_sync(0xffffffffu, vs1, msk);
        vq1 += __shfl_xor_sync(0xffffffffu, vq1, msk);
        us0 += __shfl_xor_sync(0xffffffffu, us0, msk);
        uq0 += __shfl_xor_sync(0xffffffffu, uq0, msk);
        us1 += __shfl_xor_sync(0xffffffffu, us1, msk);
        uq1 += __shfl_xor_sync(0xffffffffu, uq1, msk);
    }
    float vmu0 = vs0 * 0.015625f, vmu1 = vs1 * 0.015625f;
    float umu0 = us0 * 0.015625f, umu1 = us1 * 0.015625f;
    float vrs0 = rsqrtf(fmaf(-vmu0, vmu0, vq0 * 0.015625f) + 1e-5f);
    float vrs1 = rsqrtf(fmaf(-vmu1, vmu1, vq1 * 0.015625f) + 1e-5f);
    float urs0 = rsqrtf(fmaf(-umu0, umu0, uq0 * 0.015625f) + 1e-5f);
    float urs1 = rsqrtf(fmaf(-umu1, umu1, uq1 * 0.015625f) + 1e-5f);
    float vc0 = -vmu0 * vrs0, vc1 = -vmu1 * vrs1;
    float uc0 = -umu0 * urs0, uc1 = -umu1 * urs1;
#pragma unroll
    for (int nn = 0; nn < 8; nn++) {
        float2 g2 = *(const float2*)(pG + nn * 8 + 2 * q);
        float2 h2 = *(const float2*)(pH + nn * 8 + 2 * q);
        float t0 = fmaf(fmaf(v[nn][0], vrs0, vc0), g2.x, h2.x);
        float t1 = fmaf(fmaf(v[nn][1], vrs0, vc0), g2.y, h2.y);
        float t2 = fmaf(fmaf(v[nn][2], vrs1, vc1), g2.x, h2.x);
        float t3 = fmaf(fmaf(v[nn][3], vrs1, vc1), g2.y, h2.y);
        ap0[nn] = hmax2z(packh2(t0, t1));
        ap1[nn] = hmax2z(packh2(t2, t3));
        float s0 = fmaf(fmaf(u[nn][0], urs0, uc0), g2.x, h2.x);
        float s1 = fmaf(fmaf(u[nn][1], urs0, uc0), g2.y, h2.y);
        float s2 = fmaf(fmaf(u[nn][2], urs1, uc1), g2.x, h2.x);
        float s3 = fmaf(fmaf(u[nn][3], urs1, uc1), g2.y, h2.y);
        bp0[nn] = hmax2z(packh2(s0, s1));
        bp1[nn] = hmax2z(packh2(s2, s3));
    }
}

// 592 blocks = one exact wave at 4 blocks/SM on 148 SMs.
// block b: model m = b % 64, chunk j = b / 64. Models 0..15 have 10 blocks, 16..63 have 9.
__global__ void __launch_bounds__(128, 4) mlp_kernel(
    const float* __restrict__ x,
    const float* __restrict__ W0, const float* __restrict__ B0,
    const float* __restrict__ G0, const float* __restrict__ H0,
    const float* __restrict__ W1, const float* __restrict__ B1,
    const float* __restrict__ G1, const float* __restrict__ H1,
    const float* __restrict__ W2, const float* __restrict__ B2,
    const float* __restrict__ G2, const float* __restrict__ H2,
    const float* __restrict__ W3, const float* __restrict__ B3,
    const float* __restrict__ G3, const float* __restrict__ H3,
    const float* __restrict__ W4, const float* __restrict__ B4,
    float* __restrict__ out)
{
    extern __shared__ float sm[];
    const int tid = threadIdx.x;
    const int w = tid >> 5;
    const int lane = tid & 31;
    const int g = lane >> 2;
    const int q = lane & 3;
    const int b = blockIdx.x;
    const int m = b & 63;
    const int j = b >> 6;
    const int nb = (m < 16) ? 10 : 9;
    const int base = g_offsets[m];
    const int cnt = g_offsets[m + 1] - base;
    if (j * 128 >= cnt) return;

    // ---- build fp16 fragment-ordered weights in SMEM ----
    {
        const float* Ws[3] = { W1 + m * 4096, W2 + m * 4096, W3 + m * 4096 };
        uint2* bf = (uint2*)(sm + OFF_BF);
        for (int l = 0; l < 3; l++) {
            const float* Wl = Ws[l];
            for (int jj = tid; jj < 1024; jj += 128) {
                int ln = jj & 31, nk = jj >> 5;
                int kk = nk >> 3, nn = nk & 7;
                int n = nn * 8 + (ln >> 2);
                int kb = kk * 16 + 2 * (ln & 3);
                float2 wlo = *(const float2*)(Wl + n * 64 + kb);
                float2 whi = *(const float2*)(Wl + n * 64 + kb + 8);
                bf[l * 1024 + jj] = make_uint2(packh2(wlo.x, wlo.y), packh2(whi.x, whi.y));
            }
        }
        // layer0 k8 frags (K padded to 8; k==6 carries bias via constant-1 input)
        uint32_t* b0f = (uint32_t*)(sm + OFF_B0F);
        for (int jj = tid; jj < 256; jj += 128) {
            int ln = jj & 31, nn = jj >> 5;
            int n = nn * 8 + (ln >> 2);
            int k0 = 2 * (ln & 3);                 // 0,2,4,6
            float v0 = (k0 < 6) ? W0[m * 384 + n * 6 + k0] : B0[m * 64 + n];
            float v1 = (k0 + 1 < 6) ? W0[m * 384 + n * 6 + k0 + 1] : 0.0f;
            b0f[jj] = packh2(v0, v1);
        }
        // head k16 frags: n = ln>>2 (rows 3..7 zero), same k layout as layers
        uint2* hf = (uint2*)(sm + OFF_HF);
        {
            int ln = tid & 31, kk = tid >> 5;
            if (kk < 4) {
                int n = ln >> 2;
                uint2 v = make_uint2(0u, 0u);
                if (n < 3) {
                    int kb = kk * 16 + 2 * (ln & 3);
                    const float* Wh = W4 + m * 192 + n * 64;
                    float2 wlo = *(const float2*)(Wh + kb);
                    float2 whi = *(const float2*)(Wh + kb + 8);
                    v = make_uint2(packh2(wlo.x, wlo.y), packh2(whi.x, whi.y));
                }
                hf[tid] = v;
            }
        }
        if (tid < 64) {
            sm[OFF_GH0 + tid]       = G0[m * 64 + tid];
            sm[OFF_GH0 + 64 + tid]  = H0[m * 64 + tid];
            sm[OFF_BGH + tid]       = B1[m * 64 + tid];
            sm[OFF_BGH + 64 + tid]  = G1[m * 64 + tid];
            sm[OFF_BGH + 128 + tid] = H1[m * 64 + tid];
            sm[OFF_BGH + 192 + tid] = B2[m * 64 + tid];
            sm[OFF_BGH + 256 + tid] = G2[m * 64 + tid];
            sm[OFF_BGH + 320 + tid] = H2[m * 64 + tid];
            sm[OFF_BGH + 384 + tid] = B3[m * 64 + tid];
            sm[OFF_BGH + 448 + tid] = G3[m * 64 + tid];
            sm[OFF_BGH + 512 + tid] = H3[m * 64 + tid];
        }
        if (tid < 3) sm[OFF_B4 + tid] = B4[m * 3 + tid];
    }
    __syncthreads();

    uint32_t* stg = (uint32_t*)(sm + OFF_STAGE);
    const uint32_t* b0f = (const uint32_t*)(sm + OFF_B0F);
    const uint2* bf  = (const uint2*)(sm + OFF_BF);
    const uint2* hf  = (const uint2*)(sm + OFF_HF) + lane;
    const int rbase = w * 32;
    const float b4_0 = sm[OFF_B4 + 0];
    const float b4_1 = sm[OFF_B4 + 1];
    const float b4_2 = sm[OFF_B4 + 2];

    for (int t0 = j * 128; t0 < cnt; t0 += nb * 128) {
        const int pos = t0 + tid;
        const int posc = min(pos, cnt - 1);
        const int smp = g_perm[base + posc];

        // stage this thread's sample row as 4 f16x2 words (6 feats + 1.0 + 0)
        {
            float2 x0 = *(const float2*)(x + smp * 6);
            float2 x1 = *(const float2*)(x + smp * 6 + 2);
            float2 x2 = *(const float2*)(x + smp * 6 + 4);
            stg[tid * 4 + 0] = packh2(x0.x, x0.y);
            stg[tid * 4 + 1] = packh2(x1.x, x1.y);
            stg[tid * 4 + 2] = packh2(x2.x, x2.y);
            stg[tid * 4 + 3] = 0x00003C00u;   // {lo=1.0h (bias), hi=0}
        }
        __syncwarp();

        float d0[8][4], d1[8][4];
        uint32_t ap0[8], ap1[8], bp0[8], bp1[8];

        // ---- layer 0: both m-tiles, k8 f16 (bias folded via constant-1) ----
        {
            uint32_t a00 = stg[(rbase + g) * 4 + q];
            uint32_t a01 = stg[(rbase + g + 8) * 4 + q];
            uint32_t a10 = stg[(rbase + 16 + g) * 4 + q];
            uint32_t a11 = stg[(rbase + 24 + g) * 4 + q];
#pragma unroll
            for (int nn = 0; nn < 8; nn++) {
                d0[nn][0] = d0[nn][1] = d0[nn][2] = d0[nn][3] = 0.f;
                d1[nn][0] = d1[nn][1] = d1[nn][2] = d1[nn][3] = 0.f;
                uint32_t bb = b0f[nn * 32 + lane];
                mma_f16_k8(d0[nn], a00, a01, bb);
                mma_f16_k8(d1[nn], a10, a11, bb);
            }
        }
        ln16x2_pack(d0, d1, sm + OFF_GH0, sm + OFF_GH0 + 64, q, ap0, ap1, bp0, bp1);

        // ---- layers 1..3: k16 f16; bias as accumulator init ----
#pragma unroll 1
        for (int l = 0; l < 3; l++) {
            const float* pB = sm + OFF_BGH + l * 192;
#pragma unroll
            for (int nn = 0; nn < 8; nn++) {
                float2 bv = *(const float2*)(pB + nn * 8 + 2 * q);
                d0[nn][0] = bv.x; d0[nn][1] = bv.y; d0[nn][2] = bv.x; d0[nn][3] = bv.y;
                d1[nn][0] = bv.x; d1[nn][1] = bv.y; d1[nn][2] = bv.x; d1[nn][3] = bv.y;
            }
            const uint2* bl = bf + l * 1024 + lane;
#pragma unroll
            for (int kk = 0; kk < 4; kk++) {
#pragma unroll
                for (int nn = 0; nn < 8; nn++) {
                    uint2 bb = bl[(kk * 8 + nn) * 32];
                    mma_f16_k16(d0[nn], ap0[2 * kk], ap1[2 * kk],
                                ap0[2 * kk + 1], ap1[2 * kk + 1], bb.x, bb.y);
                    mma_f16_k16(d1[nn], bp0[2 * kk], bp1[2 * kk],
                                bp0[2 * kk + 1], bp1[2 * kk + 1], bb.x, bb.y);
                }
            }
            ln16x2_pack(d0, d1, pB + 64, pB + 128, q, ap0, ap1, bp0, bp1);
        }

        // ---- head: 64 -> 3 via mma (N padded to 8) ----
        float e0[4] = {0.f, 0.f, 0.f, 0.f};
        float e1[4] = {0.f, 0.f, 0.f, 0.f};
#pragma unroll
        for (int kk = 0; kk < 4; kk++) {
            uint2 bb = hf[kk * 32];
            mma_f16_k16(e0, ap0[2 * kk], ap1[2 * kk], ap0[2 * kk + 1], ap1[2 * kk + 1],
                        bb.x, bb.y);
            mma_f16_k16(e1, bp0[2 * kk], bp1[2 * kk], bp0[2 * kk + 1], bp1[2 * kk + 1],
                        bb.x, bb.y);
        }
        // D frag: lane(g,q) holds (row g, col 2q), (row g, col 2q+1),
        //         (row g+8, col 2q), (row g+8, col 2q+1). Valid cols: 0,1,2.
        int s_r0 = __shfl_sync(0xffffffffu, smp, g);
        int s_r1 = __shfl_sync(0xffffffffu, smp, g + 8);
        int s_r2 = __shfl_sync(0xffffffffu, smp, 16 + g);
        int s_r3 = __shfl_sync(0xffffffffu, smp, 24 + g);
        int pr = t0 + rbase + g;
        if (q == 0) {
            if (pr < cnt)      { out[s_r0 * 3 + 0] = e0[0] + b4_0; out[s_r0 * 3 + 1] = e0[1] + b4_1; }
            if (pr + 8 < cnt)  { out[s_r1 * 3 + 0] = e0[2] + b4_0; out[s_r1 * 3 + 1] = e0[3] + b4_1; }
            if (pr + 16 < cnt) { out[s_r2 * 3 + 0] = e1[0] + b4_0; out[s_r2 * 3 + 1] = e1[1] + b4_1; }
            if (pr + 24 < cnt) { out[s_r3 * 3 + 0] = e1[2] + b4_0; out[s_r3 * 3 + 1] = e1[3] + b4_1; }
        } else if (q == 1) {
            if (pr < cnt)      out[s_r0 * 3 + 2] = e0[0] + b4_2;
            if (pr + 8 < cnt)  out[s_r1 * 3 + 2] = e0[2] + b4_2;
            if (pr + 16 < cnt) out[s_r2 * 3 + 2] = e1[0] + b4_2;
            if (pr + 24 < cnt) out[s_r3 * 3 + 2] = e1[2] + b4_2;
        }
    }
}

// ---------------- launch -----------------------------------------------------
extern "C" void kernel_launch(void* const* d_in, const int* in_sizes, int n_in,
                              void* d_out, int out_size) {
    const float* x  = (const float*)d_in[0];
    const int* idx  = (const int*)d_in[1];
    const float* W0 = (const float*)d_in[2];
    const float* B0 = (const float*)d_in[3];
    const float* G0 = (const float*)d_in[4];
    const float* H0 = (const float*)d_in[5];
    const float* W1 = (const float*)d_in[6];
    const float* B1 = (const float*)d_in[7];
    const float* G1 = (const float*)d_in[8];
    const float* H1 = (const float*)d_in[9];
    const float* W2 = (const float*)d_in[10];
    const float* B2 = (const float*)d_in[11];
    const float* G2 = (const float*)d_in[12];
    const float* H2 = (const float*)d_in[13];
    const float* W3 = (const float*)d_in[14];
    const float* B3 = (const float*)d_in[15];
    const float* G3 = (const float*)d_in[16];
    const float* H3 = (const float*)d_in[17];
    const float* W4 = (const float*)d_in[18];
    const float* B4 = (const float*)d_in[19];
    float* out = (float*)d_out;

    int N = in_sizes[1];
    if (N > MAXN) N = MAXN;

    cudaFuncSetAttribute(mlp_kernel, cudaFuncAttributeMaxDynamicSharedMemorySize,
                         SMEM_FLOATS * (int)sizeof(float));

    hist_kernel<<<512, 256>>>(idx, N);
    scan_kernel<<<1, 64>>>();
    scatter_kernel<<<512, 256>>>(idx, N);

    mlp_kernel<<<592, 128, SMEM_FLOATS * (int)sizeof(float)>>>(
        x, W0, B0, G0, H0, W1, B1, G1, H1, W2, B2, G2, H2, W3, B3, G3, H3, W4, B4, out);
}